// round 1
// baseline (speedup 1.0000x reference)
#include <cuda_runtime.h>
#include <math.h>

#define TOKENS 2048
#define DIN    1024
#define DQ     256
#define NH     8
#define NQ     2048   // NH*DQ
#define NSQ    256
#define DQH    128
#define TK     10
#define NR     16384  // TOKENS*NH

// ---------------- scratch (device globals; no allocations allowed) ----------
__device__ float g_q[(size_t)TOKENS * NQ];      // 16 MB
__device__ int   g_eidx[NR * TK];
__device__ float g_ew[NR * TK];

// ---------------- Kernel 1: q = x @ Wq + bq ---------------------------------
// M=2048, N=2048, K=1024. 128x128 block tile, 8x8 per thread, BK=16.
__global__ __launch_bounds__(256) void gemm_q_kernel(const float* __restrict__ A,
                                                     const float* __restrict__ B,
                                                     const float* __restrict__ bias) {
    const int K = DIN, N = NQ;
    __shared__ __align__(16) float As[16][128];
    __shared__ __align__(16) float Bs[16][128];
    int tid = threadIdx.x;
    int bm = blockIdx.y * 128, bn = blockIdx.x * 128;
    int arow = tid >> 1, acol = (tid & 1) * 8;
    int brow = tid >> 4, bcol = (tid & 15) * 8;
    int ty = tid >> 4, tx = tid & 15;
    float acc[8][8];
#pragma unroll
    for (int i = 0; i < 8; i++)
#pragma unroll
        for (int j = 0; j < 8; j++) acc[i][j] = 0.f;

    for (int k0 = 0; k0 < K; k0 += 16) {
        const float* Ap = A + (size_t)(bm + arow) * K + k0 + acol;
        float4 a0 = *(const float4*)Ap;
        float4 a1 = *(const float4*)(Ap + 4);
        As[acol + 0][arow] = a0.x; As[acol + 1][arow] = a0.y;
        As[acol + 2][arow] = a0.z; As[acol + 3][arow] = a0.w;
        As[acol + 4][arow] = a1.x; As[acol + 5][arow] = a1.y;
        As[acol + 6][arow] = a1.z; As[acol + 7][arow] = a1.w;
        const float* Bp = B + (size_t)(k0 + brow) * N + bn + bcol;
        *(float4*)&Bs[brow][bcol]     = *(const float4*)Bp;
        *(float4*)&Bs[brow][bcol + 4] = *(const float4*)(Bp + 4);
        __syncthreads();
#pragma unroll
        for (int kk = 0; kk < 16; kk++) {
            float4 ra0 = *(float4*)&As[kk][ty * 8];
            float4 ra1 = *(float4*)&As[kk][ty * 8 + 4];
            float4 rb0 = *(float4*)&Bs[kk][tx * 8];
            float4 rb1 = *(float4*)&Bs[kk][tx * 8 + 4];
            float ra[8] = {ra0.x, ra0.y, ra0.z, ra0.w, ra1.x, ra1.y, ra1.z, ra1.w};
            float rb[8] = {rb0.x, rb0.y, rb0.z, rb0.w, rb1.x, rb1.y, rb1.z, rb1.w};
#pragma unroll
            for (int i = 0; i < 8; i++)
#pragma unroll
                for (int j = 0; j < 8; j++) acc[i][j] += ra[i] * rb[j];
        }
        __syncthreads();
    }
#pragma unroll
    for (int i = 0; i < 8; i++) {
        int m = bm + ty * 8 + i;
#pragma unroll
        for (int j = 0; j < 8; j += 4) {
            int n = bn + tx * 8 + j;
            float4 o;
            o.x = acc[i][j + 0] + bias[n + 0];
            o.y = acc[i][j + 1] + bias[n + 1];
            o.z = acc[i][j + 2] + bias[n + 2];
            o.w = acc[i][j + 3] + bias[n + 3];
            *(float4*)(g_q + (size_t)m * NQ + n) = o;
        }
    }
}

// ---------------- Kernel 2: routing (scores + double topk + softmax) --------
// 16 (token,head) rows per block, 256 threads (thread = expert column).
__global__ __launch_bounds__(256) void routing_kernel(const float* __restrict__ K1,
                                                      const float* __restrict__ K2) {
    __shared__ __align__(16) float qs[16][256];
    __shared__ float s1s[16][256];
    __shared__ float s2s[16][256];
    int tid = threadIdx.x;
    int r0 = blockIdx.x * 16;

    // load 16 q rows (16*256 floats = 1024 float4)
#pragma unroll
    for (int i = 0; i < 4; i++) {
        int idx = tid + i * 256;
        int row = idx >> 6, c4 = idx & 63;
        ((float4*)qs[row])[c4] = ((const float4*)(g_q + (size_t)(r0 + row) * DQ))[c4];
    }
    __syncthreads();

    int n = tid;  // expert index 0..255
    {
        float acc[16];
#pragma unroll
        for (int r = 0; r < 16; r++) acc[r] = 0.f;
        const float4* kr = (const float4*)(K1 + n * DQH);
#pragma unroll 4
        for (int d4 = 0; d4 < 32; d4++) {
            float4 k4 = kr[d4];
#pragma unroll
            for (int r = 0; r < 16; r++) {
                float4 q4 = ((float4*)qs[r])[d4];
                acc[r] += q4.x * k4.x + q4.y * k4.y + q4.z * k4.z + q4.w * k4.w;
            }
        }
#pragma unroll
        for (int r = 0; r < 16; r++) s1s[r][n] = acc[r];
    }
    {
        float acc[16];
#pragma unroll
        for (int r = 0; r < 16; r++) acc[r] = 0.f;
        const float4* kr = (const float4*)(K2 + n * DQH);
#pragma unroll 4
        for (int d4 = 0; d4 < 32; d4++) {
            float4 k4 = kr[d4];
#pragma unroll
            for (int r = 0; r < 16; r++) {
                float4 q4 = ((float4*)qs[r])[32 + d4];  // second half of query
                acc[r] += q4.x * k4.x + q4.y * k4.y + q4.z * k4.z + q4.w * k4.w;
            }
        }
#pragma unroll
        for (int r = 0; r < 16; r++) s2s[r][n] = acc[r];
    }
    __syncthreads();

    if (tid < 16) {
        int r = r0 + tid;
        float v1[TK], v2[TK];
        int i1a[TK], i2a[TK];
        for (int t = 0; t < TK; t++) { v1[t] = -3.0e38f; v2[t] = -3.0e38f; i1a[t] = 0; i2a[t] = 0; }
        for (int nn = 0; nn < NSQ; nn++) {
            float s = s1s[tid][nn];
            if (s > v1[TK - 1]) {
                int p = TK - 1;
                while (p > 0 && s > v1[p - 1]) { v1[p] = v1[p - 1]; i1a[p] = i1a[p - 1]; p--; }
                v1[p] = s; i1a[p] = nn;
            }
            s = s2s[tid][nn];
            if (s > v2[TK - 1]) {
                int p = TK - 1;
                while (p > 0 && s > v2[p - 1]) { v2[p] = v2[p - 1]; i2a[p] = i2a[p - 1]; p--; }
                v2[p] = s; i2a[p] = nn;
            }
        }
        // combine 10x10, take top-10 (strict > keeps earliest linear index on ties,
        // matching jax.lax.top_k stability)
        float cv[TK]; int ci[TK];
        for (int t = 0; t < TK; t++) { cv[t] = -3.0e38f; ci[t] = 0; }
        for (int i = 0; i < TK; i++) {
            for (int j = 0; j < TK; j++) {
                float s = v1[i] + v2[j];
                if (s > cv[TK - 1]) {
                    int p = TK - 1;
                    while (p > 0 && s > cv[p - 1]) { cv[p] = cv[p - 1]; ci[p] = ci[p - 1]; p--; }
                    cv[p] = s; ci[p] = i1a[i] * NSQ + i2a[j];
                }
            }
        }
        // softmax over cv (cv[0] is max)
        float m = cv[0], sum = 0.f, w[TK];
        for (int t = 0; t < TK; t++) { w[t] = expf(cv[t] - m); sum += w[t]; }
        float inv = 1.0f / sum;
        for (int t = 0; t < TK; t++) {
            g_eidx[r * TK + t] = ci[t];
            g_ew[r * TK + t]   = w[t] * inv;
        }
    }
}

// ---------------- Kernel 3: expert gather + GELU + weighted combine ---------
// 1 block per token, 256 threads (8 warps). Warp w handles head w's 10 experts.
__global__ __launch_bounds__(256) void expert_kernel(const float* __restrict__ x,
                                                     const float* __restrict__ W_up,
                                                     const float* __restrict__ W_down,
                                                     float* __restrict__ out) {
    __shared__ __align__(16) float xs[DIN];
    __shared__ float hs[80];
    __shared__ int   es[80];
    int token = blockIdx.x;
    int tid = threadIdx.x;

    ((float4*)xs)[tid] = ((const float4*)(x + (size_t)token * DIN))[tid];
    if (tid < 80) es[tid] = g_eidx[token * 80 + tid];
    __syncthreads();

    int warp = tid >> 5, lane = tid & 31;
    // Phase A: h_e = gelu(x . W_down[e]) * softmax_weight
    for (int k = 0; k < TK; k++) {
        int e = es[warp * TK + k];
        const float4* wd = (const float4*)(W_down + (size_t)e * DIN);
        const float4* x4 = (const float4*)xs;
        float acc = 0.f;
#pragma unroll
        for (int i = 0; i < 8; i++) {
            float4 w4 = wd[lane + i * 32];
            float4 v4 = x4[lane + i * 32];
            acc += w4.x * v4.x + w4.y * v4.y + w4.z * v4.z + w4.w * v4.w;
        }
#pragma unroll
        for (int off = 16; off; off >>= 1) acc += __shfl_xor_sync(0xFFFFFFFFu, acc, off);
        if (lane == 0) {
            float g = 0.5f * acc * (1.0f + erff(acc * 0.70710678118654752f));
            hs[warp * TK + k] = g * g_ew[token * 80 + warp * TK + k];
        }
    }
    __syncthreads();

    // Phase B: out[d] = sum_e h_e * W_up[e][d]; each thread owns one float4 of d
    float4 acc4 = make_float4(0.f, 0.f, 0.f, 0.f);
#pragma unroll 8
    for (int e = 0; e < 80; e++) {
        float h = hs[e];
        float4 u4 = ((const float4*)(W_up + (size_t)es[e] * DIN))[tid];
        acc4.x += h * u4.x; acc4.y += h * u4.y;
        acc4.z += h * u4.z; acc4.w += h * u4.w;
    }
    ((float4*)(out + (size_t)token * DIN))[tid] = acc4;
}

// ---------------- launch ----------------------------------------------------
extern "C" void kernel_launch(void* const* d_in, const int* in_sizes, int n_in,
                              void* d_out, int out_size) {
    const float* x      = (const float*)d_in[0];
    const float* Wq     = (const float*)d_in[1];
    const float* bq     = (const float*)d_in[2];
    const float* K1     = (const float*)d_in[3];
    const float* K2     = (const float*)d_in[4];
    const float* W_up   = (const float*)d_in[5];
    const float* W_down = (const float*)d_in[6];
    float* out = (float*)d_out;

    dim3 gg(NQ / 128, TOKENS / 128);          // 16 x 16 blocks
    gemm_q_kernel<<<gg, 256>>>(x, Wq, bq);
    routing_kernel<<<NR / 16, 256>>>(K1, K2); // 1024 blocks
    expert_kernel<<<TOKENS, 256>>>(x, W_up, W_down, out);
}

// round 2
// speedup vs baseline: 1.7432x; 1.7432x over previous
#include <cuda_runtime.h>
#include <math.h>

#define TOKENS 2048
#define DIN    1024
#define DQ     256
#define NH     8
#define NQ     2048   // NH*DQ
#define NSQ    256
#define DQH    128
#define TK     10
#define NR     16384  // TOKENS*NH
#define NEG_INF (-3.0e38f)

// ---------------- scratch (device globals; no allocations allowed) ----------
__device__ float g_q[(size_t)TOKENS * NQ];      // 16 MB
__device__ float g_K1t[DQH * NSQ];              // 128 KB transposed keys
__device__ float g_K2t[DQH * NSQ];
__device__ int   g_eidx[NR * TK];
__device__ float g_ew[NR * TK];

// ---------------- Kernel 0: transpose K1,K2 ---------------------------------
__global__ __launch_bounds__(256) void transpose_kernel(const float* __restrict__ K1,
                                                        const float* __restrict__ K2) {
    int i = blockIdx.x * 256 + threadIdx.x;   // 0..32767
    int n = i >> 7, d = i & 127;
    g_K1t[d * NSQ + n] = K1[i];
    g_K2t[d * NSQ + n] = K2[i];
}

// ---------------- Kernel 1: q = x @ Wq + bq (unchanged; at FFMA roofline) ---
__global__ __launch_bounds__(256) void gemm_q_kernel(const float* __restrict__ A,
                                                     const float* __restrict__ B,
                                                     const float* __restrict__ bias) {
    const int K = DIN, N = NQ;
    __shared__ __align__(16) float As[16][128];
    __shared__ __align__(16) float Bs[16][128];
    int tid = threadIdx.x;
    int bm = blockIdx.y * 128, bn = blockIdx.x * 128;
    int arow = tid >> 1, acol = (tid & 1) * 8;
    int brow = tid >> 4, bcol = (tid & 15) * 8;
    int ty = tid >> 4, tx = tid & 15;
    float acc[8][8];
#pragma unroll
    for (int i = 0; i < 8; i++)
#pragma unroll
        for (int j = 0; j < 8; j++) acc[i][j] = 0.f;

    for (int k0 = 0; k0 < K; k0 += 16) {
        const float* Ap = A + (size_t)(bm + arow) * K + k0 + acol;
        float4 a0 = *(const float4*)Ap;
        float4 a1 = *(const float4*)(Ap + 4);
        As[acol + 0][arow] = a0.x; As[acol + 1][arow] = a0.y;
        As[acol + 2][arow] = a0.z; As[acol + 3][arow] = a0.w;
        As[acol + 4][arow] = a1.x; As[acol + 5][arow] = a1.y;
        As[acol + 6][arow] = a1.z; As[acol + 7][arow] = a1.w;
        const float* Bp = B + (size_t)(k0 + brow) * N + bn + bcol;
        *(float4*)&Bs[brow][bcol]     = *(const float4*)Bp;
        *(float4*)&Bs[brow][bcol + 4] = *(const float4*)(Bp + 4);
        __syncthreads();
#pragma unroll
        for (int kk = 0; kk < 16; kk++) {
            float4 ra0 = *(float4*)&As[kk][ty * 8];
            float4 ra1 = *(float4*)&As[kk][ty * 8 + 4];
            float4 rb0 = *(float4*)&Bs[kk][tx * 8];
            float4 rb1 = *(float4*)&Bs[kk][tx * 8 + 4];
            float ra[8] = {ra0.x, ra0.y, ra0.z, ra0.w, ra1.x, ra1.y, ra1.z, ra1.w};
            float rb[8] = {rb0.x, rb0.y, rb0.z, rb0.w, rb1.x, rb1.y, rb1.z, rb1.w};
#pragma unroll
            for (int i = 0; i < 8; i++)
#pragma unroll
                for (int j = 0; j < 8; j++) acc[i][j] += ra[i] * rb[j];
        }
        __syncthreads();
    }
#pragma unroll
    for (int i = 0; i < 8; i++) {
        int m = bm + ty * 8 + i;
#pragma unroll
        for (int j = 0; j < 8; j += 4) {
            int n = bn + tx * 8 + j;
            float4 o;
            o.x = acc[i][j + 0] + bias[n + 0];
            o.y = acc[i][j + 1] + bias[n + 1];
            o.z = acc[i][j + 2] + bias[n + 2];
            o.w = acc[i][j + 3] + bias[n + 3];
            *(float4*)(g_q + (size_t)m * NQ + n) = o;
        }
    }
}

// ---------------- Kernel 2: routing ------------------------------------------
// Block = 16 (token,head) rows. Compute phase: thread = (4-row group, 4-expert
// quad). Topk phase: warp-parallel argmax extraction, 2 rows per warp.
__global__ __launch_bounds__(256) void routing_kernel() {
    __shared__ __align__(16) float qs[16][256];   // 16 KB
    __shared__ __align__(16) float s1s[16][256];  // 16 KB
    __shared__ __align__(16) float s2s[16][256];  // 16 KB
    int tid = threadIdx.x;
    int lane = tid & 31;
    int warp = tid >> 5;
    int r0 = blockIdx.x * 16;

    // load 16 q rows (16*256 floats)
#pragma unroll
    for (int i = 0; i < 4; i++) {
        int idx = tid + i * 256;
        int row = idx >> 6, c4 = idx & 63;
        ((float4*)qs[row])[c4] = ((const float4*)(g_q + (size_t)(r0 + row) * DQ))[c4];
    }
    __syncthreads();

    // ---- score compute: rows rg*4..rg*4+3, experts n4*4..n4*4+3 ----
    {
        int rg = tid >> 6;          // 0..3
        int n4 = tid & 63;          // float4 index over experts
        const float4* K1t4 = (const float4*)g_K1t;
        const float4* K2t4 = (const float4*)g_K2t;
        float a1[4][4], a2[4][4];
#pragma unroll
        for (int r = 0; r < 4; r++)
#pragma unroll
            for (int c = 0; c < 4; c++) { a1[r][c] = 0.f; a2[r][c] = 0.f; }
#pragma unroll 4
        for (int d = 0; d < 128; d++) {
            float4 k1 = K1t4[d * 64 + n4];
            float4 k2 = K2t4[d * 64 + n4];
#pragma unroll
            for (int r = 0; r < 4; r++) {
                float q1 = qs[rg * 4 + r][d];
                float q2 = qs[rg * 4 + r][d + 128];
                a1[r][0] += q1 * k1.x; a1[r][1] += q1 * k1.y;
                a1[r][2] += q1 * k1.z; a1[r][3] += q1 * k1.w;
                a2[r][0] += q2 * k2.x; a2[r][1] += q2 * k2.y;
                a2[r][2] += q2 * k2.z; a2[r][3] += q2 * k2.w;
            }
        }
#pragma unroll
        for (int r = 0; r < 4; r++) {
            *(float4*)&s1s[rg * 4 + r][n4 * 4] = make_float4(a1[r][0], a1[r][1], a1[r][2], a1[r][3]);
            *(float4*)&s2s[rg * 4 + r][n4 * 4] = make_float4(a2[r][0], a2[r][1], a2[r][2], a2[r][3]);
        }
    }
    __syncthreads();

    // ---- warp-parallel topk: warp handles rows 2*warp, 2*warp+1 ----
    for (int rep = 0; rep < 2; rep++) {
        int rr = warp * 2 + rep;
        int r = r0 + rr;

        // two extractions (s1, s2); lists go to s1s[rr][0..39]
        for (int list = 0; list < 2; list++) {
            float* src = (list == 0) ? s1s[rr] : s2s[rr];
            float v[8];
#pragma unroll
            for (int j = 0; j < 8; j++) v[j] = src[lane + 32 * j];
#pragma unroll 1
            for (int t = 0; t < TK; t++) {
                float mv = v[0]; int mj = 0;
#pragma unroll
                for (int j = 1; j < 8; j++)
                    if (v[j] > mv) { mv = v[j]; mj = j; }
                int mi = lane + (mj << 5);
#pragma unroll
                for (int off = 16; off; off >>= 1) {
                    float ov = __shfl_xor_sync(0xFFFFFFFFu, mv, off);
                    int   oi = __shfl_xor_sync(0xFFFFFFFFu, mi, off);
                    if (ov > mv || (ov == mv && oi < mi)) { mv = ov; mi = oi; }
                }
                if (lane == 0) {
                    s1s[rr][list * 20 + t] = mv;
                    s1s[rr][list * 20 + 10 + t] = __int_as_float(mi);
                }
                if ((mi & 31) == lane) {
                    int jj = mi >> 5;
#pragma unroll
                    for (int j = 0; j < 8; j++)
                        if (j == jj) v[j] = NEG_INF;
                }
            }
        }
        __syncwarp();

        // combine 10x10 -> top-10 by (value desc, position asc)
        float cv[4]; int cp[4];
#pragma unroll
        for (int t = 0; t < 4; t++) {
            int p = lane + 32 * t;
            if (p < 100) {
                int i = p / 10, j = p - i * 10;
                cv[t] = s1s[rr][i] + s1s[rr][20 + j];
                cp[t] = p;
            } else { cv[t] = NEG_INF; cp[t] = 127; }
        }
        float m = 0.f, sum = 0.f, myval = 0.f;
        int myidx = 0;
#pragma unroll 1
        for (int t = 0; t < TK; t++) {
            float mv = cv[0]; int mp = cp[0]; int mt = 0;
#pragma unroll
            for (int u = 1; u < 4; u++)
                if (cv[u] > mv || (cv[u] == mv && cp[u] < mp)) { mv = cv[u]; mp = cp[u]; mt = u; }
#pragma unroll
            for (int off = 16; off; off >>= 1) {
                float ov = __shfl_xor_sync(0xFFFFFFFFu, mv, off);
                int   op = __shfl_xor_sync(0xFFFFFFFFu, mp, off);
                if (ov > mv || (ov == mv && op < mp)) { mv = ov; mp = op; }
            }
            if (t == 0) m = mv;
            sum += expf(mv - m);
            int i = mp / 10, j = mp - i * 10;
            int ei = __float_as_int(s1s[rr][10 + i]) * NSQ + __float_as_int(s1s[rr][30 + j]);
            if (lane == t) { myval = mv; myidx = ei; }
            // clear winner (the lane that owns position mp)
#pragma unroll
            for (int u = 0; u < 4; u++)
                if (cp[u] == mp) cv[u] = NEG_INF;
        }
        if (lane < TK) {
            g_eidx[r * TK + lane] = myidx;
            g_ew[r * TK + lane]   = expf(myval - m) / sum;
        }
    }
}

// ---------------- Kernel 3: expert gather + GELU + weighted combine ---------
// 1 block per token, 256 threads (8 warps). Warp w handles head w's 10 experts.
__global__ __launch_bounds__(256) void expert_kernel(const float* __restrict__ x,
                                                     const float* __restrict__ W_up,
                                                     const float* __restrict__ W_down,
                                                     float* __restrict__ out) {
    __shared__ __align__(16) float xs[DIN];
    __shared__ float hs[80];
    __shared__ int   es[80];
    int token = blockIdx.x;
    int tid = threadIdx.x;

    ((float4*)xs)[tid] = ((const float4*)(x + (size_t)token * DIN))[tid];
    if (tid < 80) es[tid] = g_eidx[token * 80 + tid];
    __syncthreads();

    int warp = tid >> 5, lane = tid & 31;

    // Phase A: all 10 experts' dot products interleaved for deep MLP
    {
        const float4* wrow[TK];
#pragma unroll
        for (int k = 0; k < TK; k++)
            wrow[k] = (const float4*)(W_down + (size_t)es[warp * TK + k] * DIN);
        float acc[TK];
#pragma unroll
        for (int k = 0; k < TK; k++) acc[k] = 0.f;
        const float4* x4 = (const float4*)xs;
#pragma unroll
        for (int i = 0; i < 8; i++) {
            float4 v4 = x4[lane + i * 32];
#pragma unroll
            for (int k = 0; k < TK; k++) {
                float4 w4 = wrow[k][lane + i * 32];
                acc[k] += w4.x * v4.x + w4.y * v4.y + w4.z * v4.z + w4.w * v4.w;
            }
        }
#pragma unroll
        for (int k = 0; k < TK; k++) {
            float a = acc[k];
#pragma unroll
            for (int off = 16; off; off >>= 1) a += __shfl_xor_sync(0xFFFFFFFFu, a, off);
            if (lane == k) {
                float g = 0.5f * a * (1.0f + erff(a * 0.70710678118654752f));
                hs[warp * TK + k] = g * g_ew[token * 80 + warp * TK + k];
            }
        }
    }
    __syncthreads();

    // Phase B: out[d] = sum_e h_e * W_up[e][d]; each thread owns one float4 of d
    float4 acc4 = make_float4(0.f, 0.f, 0.f, 0.f);
#pragma unroll 10
    for (int e = 0; e < 80; e++) {
        float h = hs[e];
        float4 u4 = ((const float4*)(W_up + (size_t)es[e] * DIN))[tid];
        acc4.x += h * u4.x; acc4.y += h * u4.y;
        acc4.z += h * u4.z; acc4.w += h * u4.w;
    }
    ((float4*)(out + (size_t)token * DIN))[tid] = acc4;
}

// ---------------- launch ----------------------------------------------------
extern "C" void kernel_launch(void* const* d_in, const int* in_sizes, int n_in,
                              void* d_out, int out_size) {
    const float* x      = (const float*)d_in[0];
    const float* Wq     = (const float*)d_in[1];
    const float* bq     = (const float*)d_in[2];
    const float* K1     = (const float*)d_in[3];
    const float* K2     = (const float*)d_in[4];
    const float* W_up   = (const float*)d_in[5];
    const float* W_down = (const float*)d_in[6];
    float* out = (float*)d_out;

    transpose_kernel<<<128, 256>>>(K1, K2);
    dim3 gg(NQ / 128, TOKENS / 128);          // 16 x 16 blocks
    gemm_q_kernel<<<gg, 256>>>(x, Wq, bq);
    routing_kernel<<<NR / 16, 256>>>();       // 1024 blocks
    expert_kernel<<<TOKENS, 256>>>(x, W_up, W_down, out);
}

// round 6
// speedup vs baseline: 2.3265x; 1.3346x over previous
#include <cuda_runtime.h>
#include <cuda_bf16.h>
#include <math.h>
#include <stdint.h>

#define TOKENS 2048
#define DIN    1024
#define DQ     256
#define NH     8
#define NQ     2048   // NH*DQ
#define NSQ    256
#define DQH    128
#define TK     10
#define NR     16384  // TOKENS*NH
#define NEG_INF (-3.0e38f)

#define SPLIT_SZ ((size_t)2048 * 1024)

// ---------------- scratch (device globals; no allocations allowed) ----------
__device__ float g_q[(size_t)TOKENS * NQ];              // 16 MB
__device__ __nv_bfloat16 g_xs[2 * SPLIT_SZ];            // 8 MB  x splits [m][k] hi,lo
__device__ __nv_bfloat16 g_ws[2 * SPLIT_SZ];            // 8 MB  Wq^T splits [n][k] hi,lo
__device__ float g_K1t[DQH * NSQ];
__device__ float g_K2t[DQH * NSQ];
__device__ int   g_eidx[NR * TK];
__device__ float g_ew[NR * TK];

__device__ __forceinline__ uint32_t smem_u32(const void* p) {
    uint32_t a;
    asm("{ .reg .u64 t; cvta.to.shared.u64 t, %1; cvt.u32.u64 %0, t; }" : "=r"(a) : "l"(p));
    return a;
}

// ---------------- Kernel A: split x into 2 bf16 planes -----------------------
__global__ __launch_bounds__(256) void split_x_kernel(const float* __restrict__ x) {
    size_t i = ((size_t)blockIdx.x * 256 + threadIdx.x) * 4;
    float4 v = *(const float4*)(x + i);
    float vv[4] = {v.x, v.y, v.z, v.w};
    __nv_bfloat16 b0[4], b1[4];
#pragma unroll
    for (int c = 0; c < 4; c++) {
        b0[c] = __float2bfloat16(vv[c]);
        b1[c] = __float2bfloat16(vv[c] - __bfloat162float(b0[c]));
    }
#pragma unroll
    for (int c = 0; c < 4; c += 2) {
        *(__nv_bfloat162*)(g_xs + i + c)            = __nv_bfloat162(b0[c], b0[c + 1]);
        *(__nv_bfloat162*)(g_xs + SPLIT_SZ + i + c) = __nv_bfloat162(b1[c], b1[c + 1]);
    }
}

// ---------------- Kernel B: transpose Wq [k][n] -> [n][k] + split ------------
__global__ __launch_bounds__(256) void split_wq_kernel(const float* __restrict__ Wq) {
    __shared__ float t[32][33];
    int tx = threadIdx.x & 31, ty = threadIdx.x >> 5;
    int n0 = blockIdx.x * 32, k0 = blockIdx.y * 32;
#pragma unroll
    for (int j = 0; j < 4; j++)
        t[ty + j * 8][tx] = Wq[(size_t)(k0 + ty + j * 8) * NQ + n0 + tx];
    __syncthreads();
#pragma unroll
    for (int j = 0; j < 4; j++) {
        int nl = ty + j * 8;
        float v = t[tx][nl];
        __nv_bfloat16 b0 = __float2bfloat16(v);
        __nv_bfloat16 b1 = __float2bfloat16(v - __bfloat162float(b0));
        size_t o = (size_t)(n0 + nl) * DIN + k0 + tx;
        g_ws[o] = b0; g_ws[SPLIT_SZ + o] = b1;
    }
}

// ---------------- Kernel 0: transpose K1,K2 ---------------------------------
__global__ __launch_bounds__(256) void transpose_kernel(const float* __restrict__ K1,
                                                        const float* __restrict__ K2) {
    int i = blockIdx.x * 256 + threadIdx.x;
    int n = i >> 7, d = i & 127;
    g_K1t[d * NSQ + n] = K1[i];
    g_K2t[d * NSQ + n] = K2[i];
}

// ---------------- Kernel 1: mma.sync GEMM q = x @ Wq + bq (bf16x2, 3 prod) --
// CTA tile 128x128, 8 warps (2M x 4N), warp tile 64x32, K-chunk 32,
// cp.async double buffer. smem row stride 80B (conflict-free ldmatrix).
#define KCHUNK   32
#define NCHUNKS  32
#define ROWB     80
#define PLANE_B  (128 * ROWB)      // 10240
#define STAGE_B  (4 * PLANE_B)     // 40960
#define GEMM_SMEM (2 * STAGE_B)    // 81920

__device__ __forceinline__ void ldsm4(uint32_t* r, uint32_t addr) {
    asm volatile("ldmatrix.sync.aligned.m8n8.x4.shared.b16 {%0,%1,%2,%3}, [%4];"
                 : "=r"(r[0]), "=r"(r[1]), "=r"(r[2]), "=r"(r[3]) : "r"(addr));
}
__device__ __forceinline__ void mma16816(float* c, const uint32_t* a, const uint32_t* b) {
    asm volatile("mma.sync.aligned.m16n8k16.row.col.f32.bf16.bf16.f32 "
                 "{%0,%1,%2,%3}, {%4,%5,%6,%7}, {%8,%9}, {%0,%1,%2,%3};"
                 : "+f"(c[0]), "+f"(c[1]), "+f"(c[2]), "+f"(c[3])
                 : "r"(a[0]), "r"(a[1]), "r"(a[2]), "r"(a[3]), "r"(b[0]), "r"(b[1]));
}

__global__ __launch_bounds__(256) void gemm_tc_kernel(const float* __restrict__ bias) {
    extern __shared__ char smem[];
    uint32_t sb = smem_u32(smem);
    int tid = threadIdx.x, lane = tid & 31, warp = tid >> 5;
    int warpM = warp >> 2, warpN = warp & 3;
    int bm = blockIdx.y * 128, bn = blockIdx.x * 128;

    float acc[4][4][4];
#pragma unroll
    for (int i = 0; i < 4; i++)
#pragma unroll
        for (int j = 0; j < 4; j++)
#pragma unroll
            for (int k = 0; k < 4; k++) acc[i][j][k] = 0.f;

    // per-thread cp.async slots: idx = tid + i*256, i<8
    // plane = idx>>9 (0..3: A-hi, A-lo, B-hi, B-lo), r = (idx>>2)&127, s = idx&3
    auto issue_chunk = [&](int c) {
        int k0 = c * KCHUNK;
        uint32_t stage = sb + (c & 1) * STAGE_B;
#pragma unroll
        for (int i = 0; i < 8; i++) {
            int idx = tid + i * 256;
            int p = idx >> 9, r = (idx >> 2) & 127, s = idx & 3;
            const __nv_bfloat16* src = (p < 2)
                ? (g_xs + (size_t)p * SPLIT_SZ + (size_t)(bm + r) * DIN + k0 + s * 8)
                : (g_ws + (size_t)(p - 2) * SPLIT_SZ + (size_t)(bn + r) * DIN + k0 + s * 8);
            uint32_t sa = stage + p * PLANE_B + r * ROWB + s * 16;
            asm volatile("cp.async.cg.shared.global [%0], [%1], 16;" :: "r"(sa), "l"(src));
        }
        asm volatile("cp.async.commit_group;" ::: "memory");
    };

    issue_chunk(0);

    int g = lane >> 3, rr = lane & 7;
    for (int c = 0; c < NCHUNKS; c++) {
        if (c + 1 < NCHUNKS) {
            issue_chunk(c + 1);
            asm volatile("cp.async.wait_group 1;" ::: "memory");
        } else {
            asm volatile("cp.async.wait_group 0;" ::: "memory");
        }
        __syncthreads();
        uint32_t stage = sb + (c & 1) * STAGE_B;

#pragma unroll
        for (int k16 = 0; k16 < 2; k16++) {
            uint32_t ah[4][4], al[4][4], bh[4][2], bl[4][2];
            // A fragments: 4 m-tiles x 2 planes
#pragma unroll
            for (int mt = 0; mt < 4; mt++) {
                uint32_t rowA = warpM * 64 + mt * 16 + (g & 1) * 8 + rr;
                uint32_t seg  = k16 * 2 + (g >> 1);
                ldsm4(ah[mt], stage + 0 * PLANE_B + rowA * ROWB + seg * 16);
                ldsm4(al[mt], stage + 1 * PLANE_B + rowA * ROWB + seg * 16);
            }
            // B fragments: 2 x (n16) x 2 planes -> 4 n-tiles of 8
#pragma unroll
            for (int nb = 0; nb < 2; nb++) {
                uint32_t rowB = warpN * 32 + nb * 16 + (g >> 1) * 8 + rr;
                uint32_t seg  = k16 * 2 + (g & 1);
                uint32_t t0[4], t1[4];
                ldsm4(t0, stage + 2 * PLANE_B + rowB * ROWB + seg * 16);
                ldsm4(t1, stage + 3 * PLANE_B + rowB * ROWB + seg * 16);
                bh[nb * 2][0] = t0[0]; bh[nb * 2][1] = t0[1];
                bh[nb * 2 + 1][0] = t0[2]; bh[nb * 2 + 1][1] = t0[3];
                bl[nb * 2][0] = t1[0]; bl[nb * 2][1] = t1[1];
                bl[nb * 2 + 1][0] = t1[2]; bl[nb * 2 + 1][1] = t1[3];
            }
            // 3 products: hh, hl, lh  (product-major for accum reuse distance)
#pragma unroll
            for (int mt = 0; mt < 4; mt++)
#pragma unroll
                for (int nt = 0; nt < 4; nt++) mma16816(acc[mt][nt], ah[mt], bh[nt]);
#pragma unroll
            for (int mt = 0; mt < 4; mt++)
#pragma unroll
                for (int nt = 0; nt < 4; nt++) mma16816(acc[mt][nt], ah[mt], bl[nt]);
#pragma unroll
            for (int mt = 0; mt < 4; mt++)
#pragma unroll
                for (int nt = 0; nt < 4; nt++) mma16816(acc[mt][nt], al[mt], bh[nt]);
        }
        __syncthreads();
    }

    // epilogue: direct stores + bias
#pragma unroll
    for (int mt = 0; mt < 4; mt++) {
        int row = bm + warpM * 64 + mt * 16 + (lane >> 2);
#pragma unroll
        for (int nt = 0; nt < 4; nt++) {
            int col = bn + warpN * 32 + nt * 8 + 2 * (lane & 3);
            float b0 = bias[col], b1 = bias[col + 1];
            float2 o0 = make_float2(acc[mt][nt][0] + b0, acc[mt][nt][1] + b1);
            float2 o1 = make_float2(acc[mt][nt][2] + b0, acc[mt][nt][3] + b1);
            *(float2*)(g_q + (size_t)row * NQ + col) = o0;
            *(float2*)(g_q + (size_t)(row + 8) * NQ + col) = o1;
        }
    }
}

// ---------------- Kernel 2: routing ------------------------------------------
__global__ __launch_bounds__(256) void routing_kernel() {
    __shared__ __align__(16) float qs[16][256];
    __shared__ __align__(16) float s1s[16][256];
    __shared__ __align__(16) float s2s[16][256];
    int tid = threadIdx.x;
    int lane = tid & 31;
    int warp = tid >> 5;
    int r0 = blockIdx.x * 16;

#pragma unroll
    for (int i = 0; i < 4; i++) {
        int idx = tid + i * 256;
        int row = idx >> 6, c4 = idx & 63;
        ((float4*)qs[row])[c4] = ((const float4*)(g_q + (size_t)(r0 + row) * DQ))[c4];
    }
    __syncthreads();

    {
        int rg = tid >> 6;
        int n4 = tid & 63;
        const float4* K1t4 = (const float4*)g_K1t;
        const float4* K2t4 = (const float4*)g_K2t;
        float a1[4][4], a2[4][4];
#pragma unroll
        for (int r = 0; r < 4; r++)
#pragma unroll
            for (int cc = 0; cc < 4; cc++) { a1[r][cc] = 0.f; a2[r][cc] = 0.f; }
#pragma unroll 4
        for (int d = 0; d < 128; d++) {
            float4 k1 = K1t4[d * 64 + n4];
            float4 k2 = K2t4[d * 64 + n4];
#pragma unroll
            for (int r = 0; r < 4; r++) {
                float q1 = qs[rg * 4 + r][d];
                float q2 = qs[rg * 4 + r][d + 128];
                a1[r][0] += q1 * k1.x; a1[r][1] += q1 * k1.y;
                a1[r][2] += q1 * k1.z; a1[r][3] += q1 * k1.w;
                a2[r][0] += q2 * k2.x; a2[r][1] += q2 * k2.y;
                a2[r][2] += q2 * k2.z; a2[r][3] += q2 * k2.w;
            }
        }
#pragma unroll
        for (int r = 0; r < 4; r++) {
            *(float4*)&s1s[rg * 4 + r][n4 * 4] = make_float4(a1[r][0], a1[r][1], a1[r][2], a1[r][3]);
            *(float4*)&s2s[rg * 4 + r][n4 * 4] = make_float4(a2[r][0], a2[r][1], a2[r][2], a2[r][3]);
        }
    }
    __syncthreads();

    for (int rep = 0; rep < 2; rep++) {
        int rr = warp * 2 + rep;
        int r = r0 + rr;
        for (int list = 0; list < 2; list++) {
            float* src = (list == 0) ? s1s[rr] : s2s[rr];
            float v[8];
#pragma unroll
            for (int j = 0; j < 8; j++) v[j] = src[lane + 32 * j];
#pragma unroll 1
            for (int t = 0; t < TK; t++) {
                float mv = v[0]; int mj = 0;
#pragma unroll
                for (int j = 1; j < 8; j++)
                    if (v[j] > mv) { mv = v[j]; mj = j; }
                int mi = lane + (mj << 5);
#pragma unroll
                for (int off = 16; off; off >>= 1) {
                    float ov = __shfl_xor_sync(0xFFFFFFFFu, mv, off);
                    int   oi = __shfl_xor_sync(0xFFFFFFFFu, mi, off);
                    if (ov > mv || (ov == mv && oi < mi)) { mv = ov; mi = oi; }
                }
                if (lane == 0) {
                    s1s[rr][list * 20 + t] = mv;
                    s1s[rr][list * 20 + 10 + t] = __int_as_float(mi);
                }
                if ((mi & 31) == lane) {
                    int jj = mi >> 5;
#pragma unroll
                    for (int j = 0; j < 8; j++)
                        if (j == jj) v[j] = NEG_INF;
                }
            }
        }
        __syncwarp();

        float cv[4]; int cp[4];
#pragma unroll
        for (int t = 0; t < 4; t++) {
            int p = lane + 32 * t;
            if (p < 100) {
                int i = p / 10, j = p - i * 10;
                cv[t] = s1s[rr][i] + s1s[rr][20 + j];
                cp[t] = p;
            } else { cv[t] = NEG_INF; cp[t] = 127; }
        }
        float m = 0.f, sum = 0.f, myval = 0.f;
        int myidx = 0;
#pragma unroll 1
        for (int t = 0; t < TK; t++) {
            float mv = cv[0]; int mp = cp[0];
#pragma unroll
            for (int u = 1; u < 4; u++)
                if (cv[u] > mv || (cv[u] == mv && cp[u] < mp)) { mv = cv[u]; mp = cp[u]; }
#pragma unroll
            for (int off = 16; off; off >>= 1) {
                float ov = __shfl_xor_sync(0xFFFFFFFFu, mv, off);
                int   op = __shfl_xor_sync(0xFFFFFFFFu, mp, off);
                if (ov > mv || (ov == mv && op < mp)) { mv = ov; mp = op; }
            }
            if (t == 0) m = mv;
            sum += expf(mv - m);
            int i = mp / 10, j = mp - i * 10;
            int ei = __float_as_int(s1s[rr][10 + i]) * NSQ + __float_as_int(s1s[rr][30 + j]);
            if (lane == t) { myval = mv; myidx = ei; }
#pragma unroll
            for (int u = 0; u < 4; u++)
                if (cp[u] == mp) cv[u] = NEG_INF;
        }
        if (lane < TK) {
            g_eidx[r * TK + lane] = myidx;
            g_ew[r * TK + lane]   = expf(myval - m) / sum;
        }
    }
}

// ---------------- Kernel 3: expert gather + GELU + weighted combine ---------
__global__ __launch_bounds__(256) void expert_kernel(const float* __restrict__ x,
                                                     const float* __restrict__ W_up,
                                                     const float* __restrict__ W_down,
                                                     float* __restrict__ out) {
    __shared__ __align__(16) float xs[DIN];
    __shared__ float hs[80];
    __shared__ int   es[80];
    int token = blockIdx.x;
    int tid = threadIdx.x;

    ((float4*)xs)[tid] = ((const float4*)(x + (size_t)token * DIN))[tid];
    if (tid < 80) es[tid] = g_eidx[token * 80 + tid];
    __syncthreads();

    int warp = tid >> 5, lane = tid & 31;
    {
        const float4* wrow[TK];
#pragma unroll
        for (int k = 0; k < TK; k++)
            wrow[k] = (const float4*)(W_down + (size_t)es[warp * TK + k] * DIN);
        float acc[TK];
#pragma unroll
        for (int k = 0; k < TK; k++) acc[k] = 0.f;
        const float4* x4 = (const float4*)xs;
#pragma unroll
        for (int i = 0; i < 8; i++) {
            float4 v4 = x4[lane + i * 32];
#pragma unroll
            for (int k = 0; k < TK; k++) {
                float4 w4 = wrow[k][lane + i * 32];
                acc[k] += w4.x * v4.x + w4.y * v4.y + w4.z * v4.z + w4.w * v4.w;
            }
        }
#pragma unroll
        for (int k = 0; k < TK; k++) {
            float a = acc[k];
#pragma unroll
            for (int off = 16; off; off >>= 1) a += __shfl_xor_sync(0xFFFFFFFFu, a, off);
            if (lane == k) {
                float g = 0.5f * a * (1.0f + erff(a * 0.70710678118654752f));
                hs[warp * TK + k] = g * g_ew[token * 80 + warp * TK + k];
            }
        }
    }
    __syncthreads();

    float4 acc4 = make_float4(0.f, 0.f, 0.f, 0.f);
#pragma unroll 10
    for (int e = 0; e < 80; e++) {
        float h = hs[e];
        float4 u4 = ((const float4*)(W_up + (size_t)es[e] * DIN))[tid];
        acc4.x += h * u4.x; acc4.y += h * u4.y;
        acc4.z += h * u4.z; acc4.w += h * u4.w;
    }
    ((float4*)(out + (size_t)token * DIN))[tid] = acc4;
}

// ---------------- launch ----------------------------------------------------
extern "C" void kernel_launch(void* const* d_in, const int* in_sizes, int n_in,
                              void* d_out, int out_size) {
    const float* x      = (const float*)d_in[0];
    const float* Wq     = (const float*)d_in[1];
    const float* bq     = (const float*)d_in[2];
    const float* K1     = (const float*)d_in[3];
    const float* K2     = (const float*)d_in[4];
    const float* W_up   = (const float*)d_in[5];
    const float* W_down = (const float*)d_in[6];
    float* out = (float*)d_out;

    cudaFuncSetAttribute(gemm_tc_kernel, cudaFuncAttributeMaxDynamicSharedMemorySize, GEMM_SMEM);

    split_x_kernel<<<(TOKENS * DIN) / 1024, 256>>>(x);
    split_wq_kernel<<<dim3(NQ / 32, DIN / 32), 256>>>(Wq);
    transpose_kernel<<<128, 256>>>(K1, K2);
    gemm_tc_kernel<<<dim3(NQ / 128, TOKENS / 128), 256, GEMM_SMEM>>>(bq);
    routing_kernel<<<NR / 16, 256>>>();
    expert_kernel<<<TOKENS, 256>>>(x, W_up, W_down, out);
}

// round 7
// speedup vs baseline: 2.5565x; 1.0989x over previous
#include <cuda_runtime.h>
#include <cuda_bf16.h>
#include <math.h>
#include <stdint.h>

#define TOKENS 2048
#define DIN    1024
#define DQ     256
#define NH     8
#define NQ     2048   // NH*DQ
#define NSQ    256
#define DQH    128
#define TK     10
#define NR     16384  // TOKENS*NH
#define NEG_INF (-3.0e38f)

#define SPLIT_SZ ((size_t)2048 * 1024)
#define KSPLIT   (NSQ * DQH)          // 32768

// ---------------- scratch (device globals; no allocations allowed) ----------
__device__ __nv_bfloat16 g_qs[2 * SPLIT_SZ * 2];        // 16 MB q splits hi/lo [2048][2048]
__device__ __nv_bfloat16 g_xs[2 * SPLIT_SZ];            // 8 MB  x splits [m][k] hi,lo
__device__ __nv_bfloat16 g_ws[2 * SPLIT_SZ];            // 8 MB  Wq^T splits [n][k] hi,lo
__device__ __nv_bfloat16 g_k1s[2 * KSPLIT];             // K1 splits [n][k] hi,lo
__device__ __nv_bfloat16 g_k2s[2 * KSPLIT];
__device__ float g_s[(size_t)NR * 512];                 // 32 MB scores [row][s1|s2]
__device__ int   g_eidx[NR * TK];
__device__ float g_ew[NR * TK];

__device__ __forceinline__ uint32_t smem_u32(const void* p) {
    uint32_t a;
    asm("{ .reg .u64 t; cvta.to.shared.u64 t, %1; cvt.u32.u64 %0, t; }" : "=r"(a) : "l"(p));
    return a;
}
__device__ __forceinline__ void ldsm4(uint32_t* r, uint32_t addr) {
    asm volatile("ldmatrix.sync.aligned.m8n8.x4.shared.b16 {%0,%1,%2,%3}, [%4];"
                 : "=r"(r[0]), "=r"(r[1]), "=r"(r[2]), "=r"(r[3]) : "r"(addr));
}
__device__ __forceinline__ void mma16816(float* c, const uint32_t* a, const uint32_t* b) {
    asm volatile("mma.sync.aligned.m16n8k16.row.col.f32.bf16.bf16.f32 "
                 "{%0,%1,%2,%3}, {%4,%5,%6,%7}, {%8,%9}, {%0,%1,%2,%3};"
                 : "+f"(c[0]), "+f"(c[1]), "+f"(c[2]), "+f"(c[3])
                 : "r"(a[0]), "r"(a[1]), "r"(a[2]), "r"(a[3]), "r"(b[0]), "r"(b[1]));
}

// ---------------- Kernel A: split x into 2 bf16 planes -----------------------
__global__ __launch_bounds__(256) void split_x_kernel(const float* __restrict__ x) {
    size_t i = ((size_t)blockIdx.x * 256 + threadIdx.x) * 4;
    float4 v = *(const float4*)(x + i);
    float vv[4] = {v.x, v.y, v.z, v.w};
    __nv_bfloat16 b0[4], b1[4];
#pragma unroll
    for (int c = 0; c < 4; c++) {
        b0[c] = __float2bfloat16(vv[c]);
        b1[c] = __float2bfloat16(vv[c] - __bfloat162float(b0[c]));
    }
#pragma unroll
    for (int c = 0; c < 4; c += 2) {
        *(__nv_bfloat162*)(g_xs + i + c)            = __nv_bfloat162(b0[c], b0[c + 1]);
        *(__nv_bfloat162*)(g_xs + SPLIT_SZ + i + c) = __nv_bfloat162(b1[c], b1[c + 1]);
    }
}

// ---------------- Kernel B: transpose Wq [k][n] -> [n][k] + split ------------
__global__ __launch_bounds__(256) void split_wq_kernel(const float* __restrict__ Wq) {
    __shared__ float t[32][33];
    int tx = threadIdx.x & 31, ty = threadIdx.x >> 5;
    int n0 = blockIdx.x * 32, k0 = blockIdx.y * 32;
#pragma unroll
    for (int j = 0; j < 4; j++)
        t[ty + j * 8][tx] = Wq[(size_t)(k0 + ty + j * 8) * NQ + n0 + tx];
    __syncthreads();
#pragma unroll
    for (int j = 0; j < 4; j++) {
        int nl = ty + j * 8;
        float v = t[tx][nl];
        __nv_bfloat16 b0 = __float2bfloat16(v);
        __nv_bfloat16 b1 = __float2bfloat16(v - __bfloat162float(b0));
        size_t o = (size_t)(n0 + nl) * DIN + k0 + tx;
        g_ws[o] = b0; g_ws[SPLIT_SZ + o] = b1;
    }
}

// ---------------- Kernel C: split K1,K2 into bf16 planes --------------------
__global__ __launch_bounds__(256) void ksplit_kernel(const float* __restrict__ K1,
                                                     const float* __restrict__ K2) {
    int i = blockIdx.x * 256 + threadIdx.x;   // 0..32767
    float v1 = K1[i], v2 = K2[i];
    __nv_bfloat16 h1 = __float2bfloat16(v1);
    __nv_bfloat16 h2 = __float2bfloat16(v2);
    g_k1s[i] = h1; g_k1s[KSPLIT + i] = __float2bfloat16(v1 - __bfloat162float(h1));
    g_k2s[i] = h2; g_k2s[KSPLIT + i] = __float2bfloat16(v2 - __bfloat162float(h2));
}

// ---------------- Kernel 1: mma.sync GEMM q = x @ Wq + bq (bf16x2, 3 prod) --
#define KCHUNK   32
#define NCHUNKS  32
#define ROWB     80
#define PLANE_B  (128 * ROWB)      // 10240
#define STAGE_B  (4 * PLANE_B)     // 40960
#define GEMM_SMEM (2 * STAGE_B)    // 81920

__global__ __launch_bounds__(256) void gemm_tc_kernel(const float* __restrict__ bias) {
    extern __shared__ char smem[];
    uint32_t sb = smem_u32(smem);
    int tid = threadIdx.x, lane = tid & 31, warp = tid >> 5;
    int warpM = warp >> 2, warpN = warp & 3;
    int bm = blockIdx.y * 128, bn = blockIdx.x * 128;

    float acc[4][4][4];
#pragma unroll
    for (int i = 0; i < 4; i++)
#pragma unroll
        for (int j = 0; j < 4; j++)
#pragma unroll
            for (int k = 0; k < 4; k++) acc[i][j][k] = 0.f;

    auto issue_chunk = [&](int c) {
        int k0 = c * KCHUNK;
        uint32_t stage = sb + (c & 1) * STAGE_B;
#pragma unroll
        for (int i = 0; i < 8; i++) {
            int idx = tid + i * 256;
            int p = idx >> 9, r = (idx >> 2) & 127, s = idx & 3;
            const __nv_bfloat16* src = (p < 2)
                ? (g_xs + (size_t)p * SPLIT_SZ + (size_t)(bm + r) * DIN + k0 + s * 8)
                : (g_ws + (size_t)(p - 2) * SPLIT_SZ + (size_t)(bn + r) * DIN + k0 + s * 8);
            uint32_t sa = stage + p * PLANE_B + r * ROWB + s * 16;
            asm volatile("cp.async.cg.shared.global [%0], [%1], 16;" :: "r"(sa), "l"(src));
        }
        asm volatile("cp.async.commit_group;" ::: "memory");
    };

    issue_chunk(0);

    int g = lane >> 3, rr = lane & 7;
    for (int c = 0; c < NCHUNKS; c++) {
        if (c + 1 < NCHUNKS) {
            issue_chunk(c + 1);
            asm volatile("cp.async.wait_group 1;" ::: "memory");
        } else {
            asm volatile("cp.async.wait_group 0;" ::: "memory");
        }
        __syncthreads();
        uint32_t stage = sb + (c & 1) * STAGE_B;

#pragma unroll
        for (int k16 = 0; k16 < 2; k16++) {
            uint32_t ah[4][4], al[4][4], bh[4][2], bl[4][2];
#pragma unroll
            for (int mt = 0; mt < 4; mt++) {
                uint32_t rowA = warpM * 64 + mt * 16 + (g & 1) * 8 + rr;
                uint32_t seg  = k16 * 2 + (g >> 1);
                ldsm4(ah[mt], stage + 0 * PLANE_B + rowA * ROWB + seg * 16);
                ldsm4(al[mt], stage + 1 * PLANE_B + rowA * ROWB + seg * 16);
            }
#pragma unroll
            for (int nb = 0; nb < 2; nb++) {
                uint32_t rowB = warpN * 32 + nb * 16 + (g >> 1) * 8 + rr;
                uint32_t seg  = k16 * 2 + (g & 1);
                uint32_t t0[4], t1[4];
                ldsm4(t0, stage + 2 * PLANE_B + rowB * ROWB + seg * 16);
                ldsm4(t1, stage + 3 * PLANE_B + rowB * ROWB + seg * 16);
                bh[nb * 2][0] = t0[0]; bh[nb * 2][1] = t0[1];
                bh[nb * 2 + 1][0] = t0[2]; bh[nb * 2 + 1][1] = t0[3];
                bl[nb * 2][0] = t1[0]; bl[nb * 2][1] = t1[1];
                bl[nb * 2 + 1][0] = t1[2]; bl[nb * 2 + 1][1] = t1[3];
            }
#pragma unroll
            for (int mt = 0; mt < 4; mt++)
#pragma unroll
                for (int nt = 0; nt < 4; nt++) mma16816(acc[mt][nt], ah[mt], bh[nt]);
#pragma unroll
            for (int mt = 0; mt < 4; mt++)
#pragma unroll
                for (int nt = 0; nt < 4; nt++) mma16816(acc[mt][nt], ah[mt], bl[nt]);
#pragma unroll
            for (int mt = 0; mt < 4; mt++)
#pragma unroll
                for (int nt = 0; nt < 4; nt++) mma16816(acc[mt][nt], al[mt], bh[nt]);
        }
        __syncthreads();
    }

    // epilogue: bias add, then write q as bf16 hi/lo split pairs
#pragma unroll
    for (int mt = 0; mt < 4; mt++) {
        int row = bm + warpM * 64 + mt * 16 + (lane >> 2);
#pragma unroll
        for (int nt = 0; nt < 4; nt++) {
            int col = bn + warpN * 32 + nt * 8 + 2 * (lane & 3);
            float b0 = bias[col], b1 = bias[col + 1];
#pragma unroll
            for (int h = 0; h < 2; h++) {
                float v0 = acc[mt][nt][h * 2 + 0] + b0;
                float v1 = acc[mt][nt][h * 2 + 1] + b1;
                __nv_bfloat16 h0 = __float2bfloat16(v0);
                __nv_bfloat16 h1 = __float2bfloat16(v1);
                __nv_bfloat16 l0 = __float2bfloat16(v0 - __bfloat162float(h0));
                __nv_bfloat16 l1 = __float2bfloat16(v1 - __bfloat162float(h1));
                size_t o = (size_t)(row + h * 8) * NQ + col;
                *(__nv_bfloat162*)(g_qs + o)                = __nv_bfloat162(h0, h1);
                *(__nv_bfloat162*)(g_qs + 2 * SPLIT_SZ + o) = __nv_bfloat162(l0, l1);
            }
        }
    }
}

// ---------------- Kernel 2: score GEMM on tensor cores (bf16x2, 4 products) -
// Block: 128 reshaped-q rows x 256 experts, K=128 in one shot.
// blockIdx.x = half (0: K1/s1, 1: K2/s2), blockIdx.y = row tile.
#define SROWB   272                     // 256B row + 16B skew
#define SA_PL   (128 * SROWB)           // 34816
#define SB_PL   (256 * SROWB)           // 69632
#define SB_OFF  (2 * SA_PL)             // 69632
#define SCORE_SMEM (2 * SA_PL + 2 * SB_PL)  // 208896

__global__ __launch_bounds__(256) void score_kernel() {
    extern __shared__ char smem[];
    uint32_t sb = smem_u32(smem);
    int tid = threadIdx.x, lane = tid & 31, warp = tid >> 5;
    int warpM = warp >> 2, warpN = warp & 3;   // 2M x 4N, warp tile 64x64
    int half = blockIdx.x;
    int r0 = blockIdx.y * 128;

    // fill A: 2 planes x 128 rows x 16 segs of 16B
#pragma unroll
    for (int i = 0; i < 16; i++) {
        int idx = tid + i * 256;
        int p = idx >> 11, r = (idx >> 4) & 127, s = idx & 15;
        const __nv_bfloat16* src = g_qs + (size_t)p * 2 * SPLIT_SZ
                                 + (size_t)(r0 + r) * DQ + half * DQH + s * 8;
        asm volatile("cp.async.cg.shared.global [%0], [%1], 16;"
                     :: "r"(sb + p * SA_PL + r * SROWB + s * 16), "l"(src));
    }
    // fill B: 2 planes x 256 rows x 16 segs
    const __nv_bfloat16* kbase = half ? g_k2s : g_k1s;
#pragma unroll
    for (int i = 0; i < 32; i++) {
        int idx = tid + i * 256;
        int p = idx >> 12, r = (idx >> 4) & 255, s = idx & 15;
        const __nv_bfloat16* src = kbase + (size_t)p * KSPLIT + r * DQH + s * 8;
        asm volatile("cp.async.cg.shared.global [%0], [%1], 16;"
                     :: "r"(sb + SB_OFF + p * SB_PL + r * SROWB + s * 16), "l"(src));
    }
    asm volatile("cp.async.commit_group;" ::: "memory");
    asm volatile("cp.async.wait_group 0;" ::: "memory");
    __syncthreads();

    float acc[4][8][4];
#pragma unroll
    for (int i = 0; i < 4; i++)
#pragma unroll
        for (int j = 0; j < 8; j++)
#pragma unroll
            for (int k = 0; k < 4; k++) acc[i][j][k] = 0.f;

    int g = lane >> 3, rr = lane & 7;
#pragma unroll 1
    for (int k16 = 0; k16 < 8; k16++) {
        uint32_t ah[4][4], al[4][4], bh[8][2], bl[8][2];
#pragma unroll
        for (int mt = 0; mt < 4; mt++) {
            uint32_t rowA = warpM * 64 + mt * 16 + (g & 1) * 8 + rr;
            uint32_t seg  = k16 * 2 + (g >> 1);
            ldsm4(ah[mt], sb + 0 * SA_PL + rowA * SROWB + seg * 16);
            ldsm4(al[mt], sb + 1 * SA_PL + rowA * SROWB + seg * 16);
        }
#pragma unroll
        for (int nb = 0; nb < 4; nb++) {
            uint32_t rowB = warpN * 64 + nb * 16 + (g >> 1) * 8 + rr;
            uint32_t seg  = k16 * 2 + (g & 1);
            uint32_t t0[4], t1[4];
            ldsm4(t0, sb + SB_OFF + 0 * SB_PL + rowB * SROWB + seg * 16);
            ldsm4(t1, sb + SB_OFF + 1 * SB_PL + rowB * SROWB + seg * 16);
            bh[nb * 2][0] = t0[0]; bh[nb * 2][1] = t0[1];
            bh[nb * 2 + 1][0] = t0[2]; bh[nb * 2 + 1][1] = t0[3];
            bl[nb * 2][0] = t1[0]; bl[nb * 2][1] = t1[1];
            bl[nb * 2 + 1][0] = t1[2]; bl[nb * 2 + 1][1] = t1[3];
        }
        // 4 products: hh, hl, lh, ll  (exact in split representation)
#pragma unroll
        for (int mt = 0; mt < 4; mt++)
#pragma unroll
            for (int nt = 0; nt < 8; nt++) mma16816(acc[mt][nt], ah[mt], bh[nt]);
#pragma unroll
        for (int mt = 0; mt < 4; mt++)
#pragma unroll
            for (int nt = 0; nt < 8; nt++) mma16816(acc[mt][nt], ah[mt], bl[nt]);
#pragma unroll
        for (int mt = 0; mt < 4; mt++)
#pragma unroll
            for (int nt = 0; nt < 8; nt++) mma16816(acc[mt][nt], al[mt], bh[nt]);
#pragma unroll
        for (int mt = 0; mt < 4; mt++)
#pragma unroll
            for (int nt = 0; nt < 8; nt++) mma16816(acc[mt][nt], al[mt], bl[nt]);
    }

    // store scores
#pragma unroll
    for (int mt = 0; mt < 4; mt++) {
        int row = r0 + warpM * 64 + mt * 16 + (lane >> 2);
#pragma unroll
        for (int nt = 0; nt < 8; nt++) {
            int col = half * 256 + warpN * 64 + nt * 8 + 2 * (lane & 3);
            *(float2*)(g_s + (size_t)row * 512 + col) =
                make_float2(acc[mt][nt][0], acc[mt][nt][1]);
            *(float2*)(g_s + (size_t)(row + 8) * 512 + col) =
                make_float2(acc[mt][nt][2], acc[mt][nt][3]);
        }
    }
}

// ---------------- Kernel 3: topk + softmax -----------------------------------
__global__ __launch_bounds__(256) void topk_kernel() {
    __shared__ __align__(16) float ss[16][512];
    int tid = threadIdx.x;
    int lane = tid & 31;
    int warp = tid >> 5;
    int r0 = blockIdx.x * 16;

#pragma unroll
    for (int i = 0; i < 8; i++) {
        int idx = tid + i * 256;
        int row = idx >> 7, c4 = idx & 127;
        ((float4*)ss[row])[c4] = ((const float4*)(g_s + (size_t)(r0 + row) * 512))[c4];
    }
    __syncthreads();

    for (int rep = 0; rep < 2; rep++) {
        int rr = warp * 2 + rep;
        int r = r0 + rr;
        for (int list = 0; list < 2; list++) {
            float* src = ss[rr] + list * 256;
            float v[8];
#pragma unroll
            for (int j = 0; j < 8; j++) v[j] = src[lane + 32 * j];
#pragma unroll 1
            for (int t = 0; t < TK; t++) {
                float mv = v[0]; int mj = 0;
#pragma unroll
                for (int j = 1; j < 8; j++)
                    if (v[j] > mv) { mv = v[j]; mj = j; }
                int mi = lane + (mj << 5);
#pragma unroll
                for (int off = 16; off; off >>= 1) {
                    float ov = __shfl_xor_sync(0xFFFFFFFFu, mv, off);
                    int   oi = __shfl_xor_sync(0xFFFFFFFFu, mi, off);
                    if (ov > mv || (ov == mv && oi < mi)) { mv = ov; mi = oi; }
                }
                if (lane == 0) {
                    ss[rr][list * 20 + t] = mv;
                    ss[rr][list * 20 + 10 + t] = __int_as_float(mi);
                }
                if ((mi & 31) == lane) {
                    int jj = mi >> 5;
#pragma unroll
                    for (int j = 0; j < 8; j++)
                        if (j == jj) v[j] = NEG_INF;
                }
            }
        }
        __syncwarp();

        float cv[4]; int cp[4];
#pragma unroll
        for (int t = 0; t < 4; t++) {
            int p = lane + 32 * t;
            if (p < 100) {
                int i = p / 10, j = p - i * 10;
                cv[t] = ss[rr][i] + ss[rr][20 + j];
                cp[t] = p;
            } else { cv[t] = NEG_INF; cp[t] = 127; }
        }
        float m = 0.f, sum = 0.f, myval = 0.f;
        int myidx = 0;
#pragma unroll 1
        for (int t = 0; t < TK; t++) {
            float mv = cv[0]; int mp = cp[0];
#pragma unroll
            for (int u = 1; u < 4; u++)
                if (cv[u] > mv || (cv[u] == mv && cp[u] < mp)) { mv = cv[u]; mp = cp[u]; }
#pragma unroll
            for (int off = 16; off; off >>= 1) {
                float ov = __shfl_xor_sync(0xFFFFFFFFu, mv, off);
                int   op = __shfl_xor_sync(0xFFFFFFFFu, mp, off);
                if (ov > mv || (ov == mv && op < mp)) { mv = ov; mp = op; }
            }
            if (t == 0) m = mv;
            sum += expf(mv - m);
            int i = mp / 10, j = mp - i * 10;
            int ei = __float_as_int(ss[rr][10 + i]) * NSQ + __float_as_int(ss[rr][30 + j]);
            if (lane == t) { myval = mv; myidx = ei; }
#pragma unroll
            for (int u = 0; u < 4; u++)
                if (cp[u] == mp) cv[u] = NEG_INF;
        }
        if (lane < TK) {
            g_eidx[r * TK + lane] = myidx;
            g_ew[r * TK + lane]   = expf(myval - m) / sum;
        }
    }
}

// ---------------- Kernel 4: expert gather + GELU + weighted combine ---------
__global__ __launch_bounds__(256) void expert_kernel(const float* __restrict__ x,
                                                     const float* __restrict__ W_up,
                                                     const float* __restrict__ W_down,
                                                     float* __restrict__ out) {
    __shared__ __align__(16) float xs[DIN];
    __shared__ float hs[80];
    __shared__ int   es[80];
    int token = blockIdx.x;
    int tid = threadIdx.x;

    ((float4*)xs)[tid] = ((const float4*)(x + (size_t)token * DIN))[tid];
    if (tid < 80) es[tid] = g_eidx[token * 80 + tid];
    __syncthreads();

    int warp = tid >> 5, lane = tid & 31;
    {
        const float4* wrow[TK];
#pragma unroll
        for (int k = 0; k < TK; k++)
            wrow[k] = (const float4*)(W_down + (size_t)es[warp * TK + k] * DIN);
        float acc[TK];
#pragma unroll
        for (int k = 0; k < TK; k++) acc[k] = 0.f;
        const float4* x4 = (const float4*)xs;
#pragma unroll
        for (int i = 0; i < 8; i++) {
            float4 v4 = x4[lane + i * 32];
#pragma unroll
            for (int k = 0; k < TK; k++) {
                float4 w4 = wrow[k][lane + i * 32];
                acc[k] += w4.x * v4.x + w4.y * v4.y + w4.z * v4.z + w4.w * v4.w;
            }
        }
#pragma unroll
        for (int k = 0; k < TK; k++) {
            float a = acc[k];
#pragma unroll
            for (int off = 16; off; off >>= 1) a += __shfl_xor_sync(0xFFFFFFFFu, a, off);
            if (lane == k) {
                float g = 0.5f * a * (1.0f + erff(a * 0.70710678118654752f));
                hs[warp * TK + k] = g * g_ew[token * 80 + warp * TK + k];
            }
        }
    }
    __syncthreads();

    float4 acc4 = make_float4(0.f, 0.f, 0.f, 0.f);
#pragma unroll 10
    for (int e = 0; e < 80; e++) {
        float h = hs[e];
        float4 u4 = ((const float4*)(W_up + (size_t)es[e] * DIN))[tid];
        acc4.x += h * u4.x; acc4.y += h * u4.y;
        acc4.z += h * u4.z; acc4.w += h * u4.w;
    }
    ((float4*)(out + (size_t)token * DIN))[tid] = acc4;
}

// ---------------- launch ----------------------------------------------------
extern "C" void kernel_launch(void* const* d_in, const int* in_sizes, int n_in,
                              void* d_out, int out_size) {
    const float* x      = (const float*)d_in[0];
    const float* Wq     = (const float*)d_in[1];
    const float* bq     = (const float*)d_in[2];
    const float* K1     = (const float*)d_in[3];
    const float* K2     = (const float*)d_in[4];
    const float* W_up   = (const float*)d_in[5];
    const float* W_down = (const float*)d_in[6];
    float* out = (float*)d_out;

    cudaFuncSetAttribute(gemm_tc_kernel, cudaFuncAttributeMaxDynamicSharedMemorySize, GEMM_SMEM);
    cudaFuncSetAttribute(score_kernel, cudaFuncAttributeMaxDynamicSharedMemorySize, SCORE_SMEM);

    split_x_kernel<<<(TOKENS * DIN) / 1024, 256>>>(x);
    split_wq_kernel<<<dim3(NQ / 32, DIN / 32), 256>>>(Wq);
    ksplit_kernel<<<128, 256>>>(K1, K2);
    gemm_tc_kernel<<<dim3(NQ / 128, TOKENS / 128), 256, GEMM_SMEM>>>(bq);
    score_kernel<<<dim3(2, NR / 128), 256, SCORE_SMEM>>>();
    topk_kernel<<<NR / 16, 256>>>();
    expert_kernel<<<TOKENS, 256>>>(x, W_up, W_down, out);
}

// round 8
// speedup vs baseline: 2.5611x; 1.0018x over previous
#include <cuda_runtime.h>
#include <cuda_bf16.h>
#include <math.h>
#include <stdint.h>

#define TOKENS 2048
#define DIN    1024
#define DQ     256
#define NH     8
#define NQ     2048   // NH*DQ
#define NSQ    256
#define DQH    128
#define TK     10
#define NR     16384  // TOKENS*NH
#define NEG_INF (-3.0e38f)

#define SPLIT_SZ ((size_t)2048 * 1024)
#define KSPLIT   (NSQ * DQH)          // 32768

// ---------------- scratch (device globals; no allocations allowed) ----------
__device__ __nv_bfloat16 g_qs[2 * SPLIT_SZ * 2];        // 16 MB q splits hi/lo [2048][2048]
__device__ __nv_bfloat16 g_xs[2 * SPLIT_SZ];            // 8 MB  x splits [m][k] hi,lo
__device__ __nv_bfloat16 g_ws[2 * SPLIT_SZ];            // 8 MB  Wq^T splits [n][k] hi,lo
__device__ __nv_bfloat16 g_k1s[2 * KSPLIT];             // K1 splits [n][k] hi,lo
__device__ __nv_bfloat16 g_k2s[2 * KSPLIT];
__device__ float g_s[(size_t)NR * 512];                 // 32 MB scores [row][s1|s2]
__device__ int   g_eidx[NR * TK];
__device__ float g_ew[NR * TK];

__device__ __forceinline__ uint32_t smem_u32(const void* p) {
    uint32_t a;
    asm("{ .reg .u64 t; cvta.to.shared.u64 t, %1; cvt.u32.u64 %0, t; }" : "=r"(a) : "l"(p));
    return a;
}
__device__ __forceinline__ void ldsm4(uint32_t* r, uint32_t addr) {
    asm volatile("ldmatrix.sync.aligned.m8n8.x4.shared.b16 {%0,%1,%2,%3}, [%4];"
                 : "=r"(r[0]), "=r"(r[1]), "=r"(r[2]), "=r"(r[3]) : "r"(addr));
}
__device__ __forceinline__ void mma16816(float* c, const uint32_t* a, const uint32_t* b) {
    asm volatile("mma.sync.aligned.m16n8k16.row.col.f32.bf16.bf16.f32 "
                 "{%0,%1,%2,%3}, {%4,%5,%6,%7}, {%8,%9}, {%0,%1,%2,%3};"
                 : "+f"(c[0]), "+f"(c[1]), "+f"(c[2]), "+f"(c[3])
                 : "r"(a[0]), "r"(a[1]), "r"(a[2]), "r"(a[3]), "r"(b[0]), "r"(b[1]));
}

// ---------------- Kernel A: split x into 2 bf16 planes -----------------------
__global__ __launch_bounds__(256) void split_x_kernel(const float* __restrict__ x) {
    size_t i = ((size_t)blockIdx.x * 256 + threadIdx.x) * 4;
    float4 v = *(const float4*)(x + i);
    float vv[4] = {v.x, v.y, v.z, v.w};
    __nv_bfloat16 b0[4], b1[4];
#pragma unroll
    for (int c = 0; c < 4; c++) {
        b0[c] = __float2bfloat16(vv[c]);
        b1[c] = __float2bfloat16(vv[c] - __bfloat162float(b0[c]));
    }
#pragma unroll
    for (int c = 0; c < 4; c += 2) {
        *(__nv_bfloat162*)(g_xs + i + c)            = __nv_bfloat162(b0[c], b0[c + 1]);
        *(__nv_bfloat162*)(g_xs + SPLIT_SZ + i + c) = __nv_bfloat162(b1[c], b1[c + 1]);
    }
}

// ---------------- Kernel B: transpose Wq [k][n] -> [n][k] + split ------------
__global__ __launch_bounds__(256) void split_wq_kernel(const float* __restrict__ Wq) {
    __shared__ float t[32][33];
    int tx = threadIdx.x & 31, ty = threadIdx.x >> 5;
    int n0 = blockIdx.x * 32, k0 = blockIdx.y * 32;
#pragma unroll
    for (int j = 0; j < 4; j++)
        t[ty + j * 8][tx] = Wq[(size_t)(k0 + ty + j * 8) * NQ + n0 + tx];
    __syncthreads();
#pragma unroll
    for (int j = 0; j < 4; j++) {
        int nl = ty + j * 8;
        float v = t[tx][nl];
        __nv_bfloat16 b0 = __float2bfloat16(v);
        __nv_bfloat16 b1 = __float2bfloat16(v - __bfloat162float(b0));
        size_t o = (size_t)(n0 + nl) * DIN + k0 + tx;
        g_ws[o] = b0; g_ws[SPLIT_SZ + o] = b1;
    }
}

// ---------------- Kernel C: split K1,K2 into bf16 planes --------------------
__global__ __launch_bounds__(256) void ksplit_kernel(const float* __restrict__ K1,
                                                     const float* __restrict__ K2) {
    int i = blockIdx.x * 256 + threadIdx.x;
    float v1 = K1[i], v2 = K2[i];
    __nv_bfloat16 h1 = __float2bfloat16(v1);
    __nv_bfloat16 h2 = __float2bfloat16(v2);
    g_k1s[i] = h1; g_k1s[KSPLIT + i] = __float2bfloat16(v1 - __bfloat162float(h1));
    g_k2s[i] = h2; g_k2s[KSPLIT + i] = __float2bfloat16(v2 - __bfloat162float(h2));
}

// ---------------- Kernel 1: mma.sync GEMM q = x @ Wq + bq (bf16x2, 3 prod) --
// CTA tile 64x128 (8 warps 2Mx4N, warp 32x32), K-chunk 32, 2-stage cp.async,
// 3 CTAs/SM.
#define KCHUNK   32
#define NCHUNKS  32
#define ROWB     80
#define A_PL     (64 * ROWB)       // 5120
#define B_PL     (128 * ROWB)      // 10240
#define STAGE_B  (2 * A_PL + 2 * B_PL)   // 30720
#define GEMM_SMEM (2 * STAGE_B)          // 61440

__global__ __launch_bounds__(256, 3) void gemm_tc_kernel(const float* __restrict__ bias) {
    extern __shared__ char smem[];
    uint32_t sb = smem_u32(smem);
    int tid = threadIdx.x, lane = tid & 31, warp = tid >> 5;
    int warpM = warp >> 2, warpN = warp & 3;
    int bm = blockIdx.y * 64, bn = blockIdx.x * 128;

    float acc[2][4][4];
#pragma unroll
    for (int i = 0; i < 2; i++)
#pragma unroll
        for (int j = 0; j < 4; j++)
#pragma unroll
            for (int k = 0; k < 4; k++) acc[i][j][k] = 0.f;

    auto issue_chunk = [&](int c) {
        int k0 = c * KCHUNK;
        uint32_t stage = sb + (c & 1) * STAGE_B;
        // A: 2 planes x 64 rows x 4 segs = 512 slots
#pragma unroll
        for (int i = 0; i < 2; i++) {
            int idx = tid + i * 256;
            int p = idx >> 8, r = (idx >> 2) & 63, s = idx & 3;
            const __nv_bfloat16* src = g_xs + (size_t)p * SPLIT_SZ
                                     + (size_t)(bm + r) * DIN + k0 + s * 8;
            asm volatile("cp.async.cg.shared.global [%0], [%1], 16;"
                         :: "r"(stage + p * A_PL + r * ROWB + s * 16), "l"(src));
        }
        // B: 2 planes x 128 rows x 4 segs = 1024 slots
#pragma unroll
        for (int i = 0; i < 4; i++) {
            int idx = tid + i * 256;
            int p = idx >> 9, r = (idx >> 2) & 127, s = idx & 3;
            const __nv_bfloat16* src = g_ws + (size_t)p * SPLIT_SZ
                                     + (size_t)(bn + r) * DIN + k0 + s * 8;
            asm volatile("cp.async.cg.shared.global [%0], [%1], 16;"
                         :: "r"(stage + 2 * A_PL + p * B_PL + r * ROWB + s * 16), "l"(src));
        }
        asm volatile("cp.async.commit_group;" ::: "memory");
    };

    issue_chunk(0);

    int g = lane >> 3, rr = lane & 7;
    for (int c = 0; c < NCHUNKS; c++) {
        if (c + 1 < NCHUNKS) {
            issue_chunk(c + 1);
            asm volatile("cp.async.wait_group 1;" ::: "memory");
        } else {
            asm volatile("cp.async.wait_group 0;" ::: "memory");
        }
        __syncthreads();
        uint32_t stage = sb + (c & 1) * STAGE_B;

#pragma unroll
        for (int k16 = 0; k16 < 2; k16++) {
            uint32_t ah[2][4], al[2][4], bh[4][2], bl[4][2];
#pragma unroll
            for (int mt = 0; mt < 2; mt++) {
                uint32_t rowA = warpM * 32 + mt * 16 + (g & 1) * 8 + rr;
                uint32_t seg  = k16 * 2 + (g >> 1);
                ldsm4(ah[mt], stage + 0 * A_PL + rowA * ROWB + seg * 16);
                ldsm4(al[mt], stage + 1 * A_PL + rowA * ROWB + seg * 16);
            }
#pragma unroll
            for (int nb = 0; nb < 2; nb++) {
                uint32_t rowB = warpN * 32 + nb * 16 + (g >> 1) * 8 + rr;
                uint32_t seg  = k16 * 2 + (g & 1);
                uint32_t t0[4], t1[4];
                ldsm4(t0, stage + 2 * A_PL + 0 * B_PL + rowB * ROWB + seg * 16);
                ldsm4(t1, stage + 2 * A_PL + 1 * B_PL + rowB * ROWB + seg * 16);
                bh[nb * 2][0] = t0[0]; bh[nb * 2][1] = t0[1];
                bh[nb * 2 + 1][0] = t0[2]; bh[nb * 2 + 1][1] = t0[3];
                bl[nb * 2][0] = t1[0]; bl[nb * 2][1] = t1[1];
                bl[nb * 2 + 1][0] = t1[2]; bl[nb * 2 + 1][1] = t1[3];
            }
#pragma unroll
            for (int mt = 0; mt < 2; mt++)
#pragma unroll
                for (int nt = 0; nt < 4; nt++) mma16816(acc[mt][nt], ah[mt], bh[nt]);
#pragma unroll
            for (int mt = 0; mt < 2; mt++)
#pragma unroll
                for (int nt = 0; nt < 4; nt++) mma16816(acc[mt][nt], ah[mt], bl[nt]);
#pragma unroll
            for (int mt = 0; mt < 2; mt++)
#pragma unroll
                for (int nt = 0; nt < 4; nt++) mma16816(acc[mt][nt], al[mt], bh[nt]);
        }
        __syncthreads();
    }

    // epilogue: bias add, then write q as bf16 hi/lo split pairs
#pragma unroll
    for (int mt = 0; mt < 2; mt++) {
        int row = bm + warpM * 32 + mt * 16 + (lane >> 2);
#pragma unroll
        for (int nt = 0; nt < 4; nt++) {
            int col = bn + warpN * 32 + nt * 8 + 2 * (lane & 3);
            float b0 = bias[col], b1 = bias[col + 1];
#pragma unroll
            for (int h = 0; h < 2; h++) {
                float v0 = acc[mt][nt][h * 2 + 0] + b0;
                float v1 = acc[mt][nt][h * 2 + 1] + b1;
                __nv_bfloat16 h0 = __float2bfloat16(v0);
                __nv_bfloat16 h1 = __float2bfloat16(v1);
                __nv_bfloat16 l0 = __float2bfloat16(v0 - __bfloat162float(h0));
                __nv_bfloat16 l1 = __float2bfloat16(v1 - __bfloat162float(h1));
                size_t o = (size_t)(row + h * 8) * NQ + col;
                *(__nv_bfloat162*)(g_qs + o)                = __nv_bfloat162(h0, h1);
                *(__nv_bfloat162*)(g_qs + 2 * SPLIT_SZ + o) = __nv_bfloat162(l0, l1);
            }
        }
    }
}

// ---------------- Kernel 2: score GEMM (bf16x2, 4 products) ------------------
// CTA: 128 q-rows x 64 experts, K=128 one shot. grid (2 halves, 4 ntiles, 128).
// 8 warps 2Mx4N: warp 64 rows x 16 experts. 2 CTAs/SM.
#define SROWB   272                     // 256B row + 16B skew
#define SA_PL   (128 * SROWB)           // 34816
#define SB_PL   (64 * SROWB)            // 17408
#define SB_OFF  (2 * SA_PL)             // 69632
#define SCORE_SMEM (2 * SA_PL + 2 * SB_PL)  // 104448

__global__ __launch_bounds__(256, 2) void score_kernel() {
    extern __shared__ char smem[];
    uint32_t sb = smem_u32(smem);
    int tid = threadIdx.x, lane = tid & 31, warp = tid >> 5;
    int warpM = warp >> 2, warpN = warp & 3;
    int half = blockIdx.x;
    int n0 = blockIdx.y * 64;
    int r0 = blockIdx.z * 128;

    // A: 2 planes x 128 rows x 16 segs = 4096 slots (16/thread)
#pragma unroll
    for (int i = 0; i < 16; i++) {
        int idx = tid + i * 256;
        int p = idx >> 11, r = (idx >> 4) & 127, s = idx & 15;
        const __nv_bfloat16* src = g_qs + (size_t)p * 2 * SPLIT_SZ
                                 + (size_t)(r0 + r) * DQ + half * DQH + s * 8;
        asm volatile("cp.async.cg.shared.global [%0], [%1], 16;"
                     :: "r"(sb + p * SA_PL + r * SROWB + s * 16), "l"(src));
    }
    // B: 2 planes x 64 rows x 16 segs = 2048 slots (8/thread)
    const __nv_bfloat16* kbase = half ? g_k2s : g_k1s;
#pragma unroll
    for (int i = 0; i < 8; i++) {
        int idx = tid + i * 256;
        int p = idx >> 10, r = (idx >> 4) & 63, s = idx & 15;
        const __nv_bfloat16* src = kbase + (size_t)p * KSPLIT + (n0 + r) * DQH + s * 8;
        asm volatile("cp.async.cg.shared.global [%0], [%1], 16;"
                     :: "r"(sb + SB_OFF + p * SB_PL + r * SROWB + s * 16), "l"(src));
    }
    asm volatile("cp.async.commit_group;" ::: "memory");
    asm volatile("cp.async.wait_group 0;" ::: "memory");
    __syncthreads();

    float acc[4][2][4];
#pragma unroll
    for (int i = 0; i < 4; i++)
#pragma unroll
        for (int j = 0; j < 2; j++)
#pragma unroll
            for (int k = 0; k < 4; k++) acc[i][j][k] = 0.f;

    int g = lane >> 3, rr = lane & 7;
#pragma unroll 1
    for (int k16 = 0; k16 < 8; k16++) {
        uint32_t ah[4][4], al[4][4], bh[2][2], bl[2][2];
#pragma unroll
        for (int mt = 0; mt < 4; mt++) {
            uint32_t rowA = warpM * 64 + mt * 16 + (g & 1) * 8 + rr;
            uint32_t seg  = k16 * 2 + (g >> 1);
            ldsm4(ah[mt], sb + 0 * SA_PL + rowA * SROWB + seg * 16);
            ldsm4(al[mt], sb + 1 * SA_PL + rowA * SROWB + seg * 16);
        }
        {
            uint32_t rowB = warpN * 16 + (g >> 1) * 8 + rr;
            uint32_t seg  = k16 * 2 + (g & 1);
            uint32_t t0[4], t1[4];
            ldsm4(t0, sb + SB_OFF + 0 * SB_PL + rowB * SROWB + seg * 16);
            ldsm4(t1, sb + SB_OFF + 1 * SB_PL + rowB * SROWB + seg * 16);
            bh[0][0] = t0[0]; bh[0][1] = t0[1]; bh[1][0] = t0[2]; bh[1][1] = t0[3];
            bl[0][0] = t1[0]; bl[0][1] = t1[1]; bl[1][0] = t1[2]; bl[1][1] = t1[3];
        }
#pragma unroll
        for (int mt = 0; mt < 4; mt++)
#pragma unroll
            for (int nt = 0; nt < 2; nt++) mma16816(acc[mt][nt], ah[mt], bh[nt]);
#pragma unroll
        for (int mt = 0; mt < 4; mt++)
#pragma unroll
            for (int nt = 0; nt < 2; nt++) mma16816(acc[mt][nt], ah[mt], bl[nt]);
#pragma unroll
        for (int mt = 0; mt < 4; mt++)
#pragma unroll
            for (int nt = 0; nt < 2; nt++) mma16816(acc[mt][nt], al[mt], bh[nt]);
#pragma unroll
        for (int mt = 0; mt < 4; mt++)
#pragma unroll
            for (int nt = 0; nt < 2; nt++) mma16816(acc[mt][nt], al[mt], bl[nt]);
    }

#pragma unroll
    for (int mt = 0; mt < 4; mt++) {
        int row = r0 + warpM * 64 + mt * 16 + (lane >> 2);
#pragma unroll
        for (int nt = 0; nt < 2; nt++) {
            int col = half * 256 + n0 + warpN * 16 + nt * 8 + 2 * (lane & 3);
            *(float2*)(g_s + (size_t)row * 512 + col) =
                make_float2(acc[mt][nt][0], acc[mt][nt][1]);
            *(float2*)(g_s + (size_t)(row + 8) * 512 + col) =
                make_float2(acc[mt][nt][2], acc[mt][nt][3]);
        }
    }
}

// ---------------- Kernel 3: topk + softmax (1 warp per row) ------------------
__global__ __launch_bounds__(512) void topk_kernel() {
    __shared__ __align__(16) float ss[16][512];
    int tid = threadIdx.x;
    int lane = tid & 31;
    int warp = tid >> 5;       // 0..15, one row each
    int r0 = blockIdx.x * 16;

#pragma unroll
    for (int i = 0; i < 4; i++) {
        int idx = tid + i * 512;
        int row = idx >> 7, c4 = idx & 127;
        ((float4*)ss[row])[c4] = ((const float4*)(g_s + (size_t)(r0 + row) * 512))[c4];
    }
    __syncthreads();

    int rr = warp;
    int r = r0 + rr;
    for (int list = 0; list < 2; list++) {
        float* src = ss[rr] + list * 256;
        float v[8];
#pragma unroll
        for (int j = 0; j < 8; j++) v[j] = src[lane + 32 * j];
#pragma unroll 1
        for (int t = 0; t < TK; t++) {
            float mv = v[0]; int mj = 0;
#pragma unroll
            for (int j = 1; j < 8; j++)
                if (v[j] > mv) { mv = v[j]; mj = j; }
            int mi = lane + (mj << 5);
#pragma unroll
            for (int off = 16; off; off >>= 1) {
                float ov = __shfl_xor_sync(0xFFFFFFFFu, mv, off);
                int   oi = __shfl_xor_sync(0xFFFFFFFFu, mi, off);
                if (ov > mv || (ov == mv && oi < mi)) { mv = ov; mi = oi; }
            }
            if (lane == 0) {
                ss[rr][list * 20 + t] = mv;
                ss[rr][list * 20 + 10 + t] = __int_as_float(mi);
            }
            if ((mi & 31) == lane) {
                int jj = mi >> 5;
#pragma unroll
                for (int j = 0; j < 8; j++)
                    if (j == jj) v[j] = NEG_INF;
            }
        }
    }
    __syncwarp();

    float cv[4]; int cp[4];
#pragma unroll
    for (int t = 0; t < 4; t++) {
        int p = lane + 32 * t;
        if (p < 100) {
            int i = p / 10, j = p - i * 10;
            cv[t] = ss[rr][i] + ss[rr][20 + j];
            cp[t] = p;
        } else { cv[t] = NEG_INF; cp[t] = 127; }
    }
    float m = 0.f, sum = 0.f, myval = 0.f;
    int myidx = 0;
#pragma unroll 1
    for (int t = 0; t < TK; t++) {
        float mv = cv[0]; int mp = cp[0];
#pragma unroll
        for (int u = 1; u < 4; u++)
            if (cv[u] > mv || (cv[u] == mv && cp[u] < mp)) { mv = cv[u]; mp = cp[u]; }
#pragma unroll
        for (int off = 16; off; off >>= 1) {
            float ov = __shfl_xor_sync(0xFFFFFFFFu, mv, off);
            int   op = __shfl_xor_sync(0xFFFFFFFFu, mp, off);
            if (ov > mv || (ov == mv && op < mp)) { mv = ov; mp = op; }
        }
        if (t == 0) m = mv;
        sum += expf(mv - m);
        int i = mp / 10, j = mp - i * 10;
        int ei = __float_as_int(ss[rr][10 + i]) * NSQ + __float_as_int(ss[rr][30 + j]);
        if (lane == t) { myval = mv; myidx = ei; }
#pragma unroll
        for (int u = 0; u < 4; u++)
            if (cp[u] == mp) cv[u] = NEG_INF;
    }
    if (lane < TK) {
        g_eidx[r * TK + lane] = myidx;
        g_ew[r * TK + lane]   = expf(myval - m) / sum;
    }
}

// ---------------- Kernel 4: expert gather + GELU + weighted combine ---------
__global__ __launch_bounds__(256) void expert_kernel(const float* __restrict__ x,
                                                     const float* __restrict__ W_up,
                                                     const float* __restrict__ W_down,
                                                     float* __restrict__ out) {
    __shared__ __align__(16) float xs[DIN];
    __shared__ float hs[80];
    __shared__ int   es[80];
    int token = blockIdx.x;
    int tid = threadIdx.x;

    ((float4*)xs)[tid] = ((const float4*)(x + (size_t)token * DIN))[tid];
    if (tid < 80) es[tid] = g_eidx[token * 80 + tid];
    __syncthreads();

    int warp = tid >> 5, lane = tid & 31;
    {
        const float4* wrow[TK];
#pragma unroll
        for (int k = 0; k < TK; k++)
            wrow[k] = (const float4*)(W_down + (size_t)es[warp * TK + k] * DIN);
        float acc[TK];
#pragma unroll
        for (int k = 0; k < TK; k++) acc[k] = 0.f;
        const float4* x4 = (const float4*)xs;
#pragma unroll
        for (int i = 0; i < 8; i++) {
            float4 v4 = x4[lane + i * 32];
#pragma unroll
            for (int k = 0; k < TK; k++) {
                float4 w4 = wrow[k][lane + i * 32];
                acc[k] += w4.x * v4.x + w4.y * v4.y + w4.z * v4.z + w4.w * v4.w;
            }
        }
#pragma unroll
        for (int k = 0; k < TK; k++) {
            float a = acc[k];
#pragma unroll
            for (int off = 16; off; off >>= 1) a += __shfl_xor_sync(0xFFFFFFFFu, a, off);
            if (lane == k) {
                float g = 0.5f * a * (1.0f + erff(a * 0.70710678118654752f));
                hs[warp * TK + k] = g * g_ew[token * 80 + warp * TK + k];
            }
        }
    }
    __syncthreads();

    float4 acc4 = make_float4(0.f, 0.f, 0.f, 0.f);
#pragma unroll 10
    for (int e = 0; e < 80; e++) {
        float h = hs[e];
        float4 u4 = ((const float4*)(W_up + (size_t)es[e] * DIN))[tid];
        acc4.x += h * u4.x; acc4.y += h * u4.y;
        acc4.z += h * u4.z; acc4.w += h * u4.w;
    }
    ((float4*)(out + (size_t)token * DIN))[tid] = acc4;
}

// ---------------- launch ----------------------------------------------------
extern "C" void kernel_launch(void* const* d_in, const int* in_sizes, int n_in,
                              void* d_out, int out_size) {
    const float* x      = (const float*)d_in[0];
    const float* Wq     = (const float*)d_in[1];
    const float* bq     = (const float*)d_in[2];
    const float* K1     = (const float*)d_in[3];
    const float* K2     = (const float*)d_in[4];
    const float* W_up   = (const float*)d_in[5];
    const float* W_down = (const float*)d_in[6];
    float* out = (float*)d_out;

    cudaFuncSetAttribute(gemm_tc_kernel, cudaFuncAttributeMaxDynamicSharedMemorySize, GEMM_SMEM);
    cudaFuncSetAttribute(score_kernel, cudaFuncAttributeMaxDynamicSharedMemorySize, SCORE_SMEM);

    split_x_kernel<<<(TOKENS * DIN) / 1024, 256>>>(x);
    split_wq_kernel<<<dim3(NQ / 32, DIN / 32), 256>>>(Wq);
    ksplit_kernel<<<128, 256>>>(K1, K2);
    gemm_tc_kernel<<<dim3(NQ / 128, TOKENS / 64), 256, GEMM_SMEM>>>(bq);
    score_kernel<<<dim3(2, 4, NR / 128), 256, SCORE_SMEM>>>();
    topk_kernel<<<NR / 16, 512>>>();
    expert_kernel<<<TOKENS, 256>>>(x, W_up, W_down, out);
}

// round 10
// speedup vs baseline: 2.5618x; 1.0003x over previous
#include <cuda_runtime.h>
#include <cuda_bf16.h>
#include <math.h>
#include <stdint.h>

#define TOKENS 2048
#define DIN    1024
#define DQ     256
#define NH     8
#define NQ     2048   // NH*DQ
#define NSQ    256
#define DQH    128
#define TK     10
#define NR     16384  // TOKENS*NH
#define NEG_INF (-3.0e38f)

#define SPLIT_SZ ((size_t)2048 * 1024)
#define KSPLIT   (NSQ * DQH)          // 32768

// ---------------- scratch (device globals; no allocations allowed) ----------
__device__ __nv_bfloat16 g_qs[2 * SPLIT_SZ * 2];        // 16 MB q splits hi/lo [2048][2048]
__device__ __nv_bfloat16 g_xs[2 * SPLIT_SZ];            // 8 MB  x splits [m][k] hi,lo
__device__ __nv_bfloat16 g_ws[2 * SPLIT_SZ];            // 8 MB  Wq^T splits [n][k] hi,lo
__device__ __nv_bfloat16 g_k1s[2 * KSPLIT];             // K1 splits [n][k] hi,lo
__device__ __nv_bfloat16 g_k2s[2 * KSPLIT];
__device__ float g_s[(size_t)NR * 512];                 // 32 MB scores [row][s1|s2]
__device__ int   g_eidx[NR * TK];
__device__ float g_ew[NR * TK];

__device__ __forceinline__ uint32_t smem_u32(const void* p) {
    uint32_t a;
    asm("{ .reg .u64 t; cvta.to.shared.u64 t, %1; cvt.u32.u64 %0, t; }" : "=r"(a) : "l"(p));
    return a;
}
__device__ __forceinline__ void ldsm4(uint32_t* r, uint32_t addr) {
    asm volatile("ldmatrix.sync.aligned.m8n8.x4.shared.b16 {%0,%1,%2,%3}, [%4];"
                 : "=r"(r[0]), "=r"(r[1]), "=r"(r[2]), "=r"(r[3]) : "r"(addr));
}
__device__ __forceinline__ void mma16816(float* c, const uint32_t* a, const uint32_t* b) {
    asm volatile("mma.sync.aligned.m16n8k16.row.col.f32.bf16.bf16.f32 "
                 "{%0,%1,%2,%3}, {%4,%5,%6,%7}, {%8,%9}, {%0,%1,%2,%3};"
                 : "+f"(c[0]), "+f"(c[1]), "+f"(c[2]), "+f"(c[3])
                 : "r"(a[0]), "r"(a[1]), "r"(a[2]), "r"(a[3]), "r"(b[0]), "r"(b[1]));
}

// ---------------- Kernel A: split x into 2 bf16 planes -----------------------
__global__ __launch_bounds__(256) void split_x_kernel(const float* __restrict__ x) {
    size_t i = ((size_t)blockIdx.x * 256 + threadIdx.x) * 4;
    float4 v = *(const float4*)(x + i);
    float vv[4] = {v.x, v.y, v.z, v.w};
    __nv_bfloat16 b0[4], b1[4];
#pragma unroll
    for (int c = 0; c < 4; c++) {
        b0[c] = __float2bfloat16(vv[c]);
        b1[c] = __float2bfloat16(vv[c] - __bfloat162float(b0[c]));
    }
#pragma unroll
    for (int c = 0; c < 4; c += 2) {
        *(__nv_bfloat162*)(g_xs + i + c)            = __nv_bfloat162(b0[c], b0[c + 1]);
        *(__nv_bfloat162*)(g_xs + SPLIT_SZ + i + c) = __nv_bfloat162(b1[c], b1[c + 1]);
    }
}

// ---------------- Kernel B: transpose Wq [k][n] -> [n][k] + split ------------
__global__ __launch_bounds__(256) void split_wq_kernel(const float* __restrict__ Wq) {
    __shared__ float t[32][33];
    int tx = threadIdx.x & 31, ty = threadIdx.x >> 5;
    int n0 = blockIdx.x * 32, k0 = blockIdx.y * 32;
#pragma unroll
    for (int j = 0; j < 4; j++)
        t[ty + j * 8][tx] = Wq[(size_t)(k0 + ty + j * 8) * NQ + n0 + tx];
    __syncthreads();
#pragma unroll
    for (int j = 0; j < 4; j++) {
        int nl = ty + j * 8;
        float v = t[tx][nl];
        __nv_bfloat16 b0 = __float2bfloat16(v);
        __nv_bfloat16 b1 = __float2bfloat16(v - __bfloat162float(b0));
        size_t o = (size_t)(n0 + nl) * DIN + k0 + tx;
        g_ws[o] = b0; g_ws[SPLIT_SZ + o] = b1;
    }
}

// ---------------- Kernel C: split K1,K2 into bf16 planes --------------------
__global__ __launch_bounds__(256) void ksplit_kernel(const float* __restrict__ K1,
                                                     const float* __restrict__ K2) {
    int i = blockIdx.x * 256 + threadIdx.x;
    float v1 = K1[i], v2 = K2[i];
    __nv_bfloat16 h1 = __float2bfloat16(v1);
    __nv_bfloat16 h2 = __float2bfloat16(v2);
    g_k1s[i] = h1; g_k1s[KSPLIT + i] = __float2bfloat16(v1 - __bfloat162float(h1));
    g_k2s[i] = h2; g_k2s[KSPLIT + i] = __float2bfloat16(v2 - __bfloat162float(h2));
}

// ---------------- Kernel 1: mma.sync GEMM q = x @ Wq + bq (bf16x2, 3 prod) --
// CTA tile 128x128 (8 warps 2Mx4N, warp 64x32), K-chunk 16, 4-stage cp.async
// ring (prefetch depth 3), 2 CTAs/SM.
#define KCHUNK   16
#define NCHUNKS  64
#define ROWB     48                    // 32B data + 16B skew
#define PLANE_B  (128 * ROWB)          // 6144
#define STAGE_B  (4 * PLANE_B)         // 24576
#define GEMM_SMEM (4 * STAGE_B)        // 98304

__global__ __launch_bounds__(256, 2) void gemm_tc_kernel(const float* __restrict__ bias) {
    extern __shared__ char smem[];
    uint32_t sb = smem_u32(smem);
    int tid = threadIdx.x, lane = tid & 31, warp = tid >> 5;
    int warpM = warp >> 2, warpN = warp & 3;
    int bm = blockIdx.y * 128, bn = blockIdx.x * 128;

    float acc[4][4][4];
#pragma unroll
    for (int i = 0; i < 4; i++)
#pragma unroll
        for (int j = 0; j < 4; j++)
#pragma unroll
            for (int k = 0; k < 4; k++) acc[i][j][k] = 0.f;

    // chunk -> 4 planes (A-hi, A-lo, B-hi, B-lo) x 128 rows x 2 segs of 16B
    auto issue_chunk = [&](int c) {
        int k0 = c * KCHUNK;
        uint32_t stage = sb + (c & 3) * STAGE_B;
#pragma unroll
        for (int i = 0; i < 4; i++) {
            int idx = tid + i * 256;
            int p = idx >> 8, r = (idx >> 1) & 127, s = idx & 1;
            const __nv_bfloat16* src = (p < 2)
                ? (g_xs + (size_t)p * SPLIT_SZ + (size_t)(bm + r) * DIN + k0 + s * 8)
                : (g_ws + (size_t)(p - 2) * SPLIT_SZ + (size_t)(bn + r) * DIN + k0 + s * 8);
            asm volatile("cp.async.cg.shared.global [%0], [%1], 16;"
                         :: "r"(stage + p * PLANE_B + r * ROWB + s * 16), "l"(src));
        }
        asm volatile("cp.async.commit_group;" ::: "memory");
    };

    issue_chunk(0); issue_chunk(1); issue_chunk(2);

    int g = lane >> 3, rr = lane & 7;
    for (int c = 0; c < NCHUNKS; c++) {
        asm volatile("cp.async.wait_group 2;" ::: "memory");
        __syncthreads();
        if (c + 3 < NCHUNKS) issue_chunk(c + 3);
        else asm volatile("cp.async.commit_group;" ::: "memory");  // empty group, keeps count uniform

        uint32_t stage = sb + (c & 3) * STAGE_B;
        uint32_t ah[4][4], al[4][4], bh[4][2], bl[4][2];
#pragma unroll
        for (int mt = 0; mt < 4; mt++) {
            uint32_t rowA = warpM * 64 + mt * 16 + (g & 1) * 8 + rr;
            uint32_t seg  = g >> 1;
            ldsm4(ah[mt], stage + 0 * PLANE_B + rowA * ROWB + seg * 16);
            ldsm4(al[mt], stage + 1 * PLANE_B + rowA * ROWB + seg * 16);
        }
#pragma unroll
        for (int nb = 0; nb < 2; nb++) {
            uint32_t rowB = warpN * 32 + nb * 16 + (g >> 1) * 8 + rr;
            uint32_t seg  = g & 1;
            uint32_t t0[4], t1[4];
            ldsm4(t0, stage + 2 * PLANE_B + rowB * ROWB + seg * 16);
            ldsm4(t1, stage + 3 * PLANE_B + rowB * ROWB + seg * 16);
            bh[nb * 2][0] = t0[0]; bh[nb * 2][1] = t0[1];
            bh[nb * 2 + 1][0] = t0[2]; bh[nb * 2 + 1][1] = t0[3];
            bl[nb * 2][0] = t1[0]; bl[nb * 2][1] = t1[1];
            bl[nb * 2 + 1][0] = t1[2]; bl[nb * 2 + 1][1] = t1[3];
        }
#pragma unroll
        for (int mt = 0; mt < 4; mt++)
#pragma unroll
            for (int nt = 0; nt < 4; nt++) mma16816(acc[mt][nt], ah[mt], bh[nt]);
#pragma unroll
        for (int mt = 0; mt < 4; mt++)
#pragma unroll
            for (int nt = 0; nt < 4; nt++) mma16816(acc[mt][nt], ah[mt], bl[nt]);
#pragma unroll
        for (int mt = 0; mt < 4; mt++)
#pragma unroll
            for (int nt = 0; nt < 4; nt++) mma16816(acc[mt][nt], al[mt], bh[nt]);
    }

    // epilogue: bias add, then write q as bf16 hi/lo split pairs
#pragma unroll
    for (int mt = 0; mt < 4; mt++) {
        int row = bm + warpM * 64 + mt * 16 + (lane >> 2);
#pragma unroll
        for (int nt = 0; nt < 4; nt++) {
            int col = bn + warpN * 32 + nt * 8 + 2 * (lane & 3);
            float b0 = bias[col], b1 = bias[col + 1];
#pragma unroll
            for (int h = 0; h < 2; h++) {
                float v0 = acc[mt][nt][h * 2 + 0] + b0;
                float v1 = acc[mt][nt][h * 2 + 1] + b1;
                __nv_bfloat16 h0 = __float2bfloat16(v0);
                __nv_bfloat16 h1 = __float2bfloat16(v1);
                __nv_bfloat16 l0 = __float2bfloat16(v0 - __bfloat162float(h0));
                __nv_bfloat16 l1 = __float2bfloat16(v1 - __bfloat162float(h1));
                size_t o = (size_t)(row + h * 8) * NQ + col;
                *(__nv_bfloat162*)(g_qs + o)                = __nv_bfloat162(h0, h1);
                *(__nv_bfloat162*)(g_qs + 2 * SPLIT_SZ + o) = __nv_bfloat162(l0, l1);
            }
        }
    }
}

// ---------------- Kernel 2: score GEMM (bf16x2, 4 products) ------------------
// CTA: 128 q-rows x 64 experts, K=128 one shot. grid (2 halves, 4 ntiles, 128).
// 8 warps 2Mx4N: warp 64 rows x 16 experts. 2 CTAs/SM.
#define SROWB   272                     // 256B row + 16B skew
#define SA_PL   (128 * SROWB)           // 34816
#define SB_PL   (64 * SROWB)            // 17408
#define SB_OFF  (2 * SA_PL)             // 69632
#define SCORE_SMEM (2 * SA_PL + 2 * SB_PL)  // 104448

__global__ __launch_bounds__(256, 2) void score_kernel() {
    extern __shared__ char smem[];
    uint32_t sb = smem_u32(smem);
    int tid = threadIdx.x, lane = tid & 31, warp = tid >> 5;
    int warpM = warp >> 2, warpN = warp & 3;
    int half = blockIdx.x;
    int n0 = blockIdx.y * 64;
    int r0 = blockIdx.z * 128;

#pragma unroll
    for (int i = 0; i < 16; i++) {
        int idx = tid + i * 256;
        int p = idx >> 11, r = (idx >> 4) & 127, s = idx & 15;
        const __nv_bfloat16* src = g_qs + (size_t)p * 2 * SPLIT_SZ
                                 + (size_t)(r0 + r) * DQ + half * DQH + s * 8;
        asm volatile("cp.async.cg.shared.global [%0], [%1], 16;"
                     :: "r"(sb + p * SA_PL + r * SROWB + s * 16), "l"(src));
    }
    const __nv_bfloat16* kbase = half ? g_k2s : g_k1s;
#pragma unroll
    for (int i = 0; i < 8; i++) {
        int idx = tid + i * 256;
        int p = idx >> 10, r = (idx >> 4) & 63, s = idx & 15;
        const __nv_bfloat16* src = kbase + (size_t)p * KSPLIT + (n0 + r) * DQH + s * 8;
        asm volatile("cp.async.cg.shared.global [%0], [%1], 16;"
                     :: "r"(sb + SB_OFF + p * SB_PL + r * SROWB + s * 16), "l"(src));
    }
    asm volatile("cp.async.commit_group;" ::: "memory");
    asm volatile("cp.async.wait_group 0;" ::: "memory");
    __syncthreads();

    float acc[4][2][4];
#pragma unroll
    for (int i = 0; i < 4; i++)
#pragma unroll
        for (int j = 0; j < 2; j++)
#pragma unroll
            for (int k = 0; k < 4; k++) acc[i][j][k] = 0.f;

    int g = lane >> 3, rr = lane & 7;
#pragma unroll 1
    for (int k16 = 0; k16 < 8; k16++) {
        uint32_t ah[4][4], al[4][4], bh[2][2], bl[2][2];
#pragma unroll
        for (int mt = 0; mt < 4; mt++) {
            uint32_t rowA = warpM * 64 + mt * 16 + (g & 1) * 8 + rr;
            uint32_t seg  = k16 * 2 + (g >> 1);
            ldsm4(ah[mt], sb + 0 * SA_PL + rowA * SROWB + seg * 16);
            ldsm4(al[mt], sb + 1 * SA_PL + rowA * SROWB + seg * 16);
        }
        {
            uint32_t rowB = warpN * 16 + (g >> 1) * 8 + rr;
            uint32_t seg  = k16 * 2 + (g & 1);
            uint32_t t0[4], t1[4];
            ldsm4(t0, sb + SB_OFF + 0 * SB_PL + rowB * SROWB + seg * 16);
            ldsm4(t1, sb + SB_OFF + 1 * SB_PL + rowB * SROWB + seg * 16);
            bh[0][0] = t0[0]; bh[0][1] = t0[1]; bh[1][0] = t0[2]; bh[1][1] = t0[3];
            bl[0][0] = t1[0]; bl[0][1] = t1[1]; bl[1][0] = t1[2]; bl[1][1] = t1[3];
        }
#pragma unroll
        for (int mt = 0; mt < 4; mt++)
#pragma unroll
            for (int nt = 0; nt < 2; nt++) mma16816(acc[mt][nt], ah[mt], bh[nt]);
#pragma unroll
        for (int mt = 0; mt < 4; mt++)
#pragma unroll
            for (int nt = 0; nt < 2; nt++) mma16816(acc[mt][nt], ah[mt], bl[nt]);
#pragma unroll
        for (int mt = 0; mt < 4; mt++)
#pragma unroll
            for (int nt = 0; nt < 2; nt++) mma16816(acc[mt][nt], al[mt], bh[nt]);
#pragma unroll
        for (int mt = 0; mt < 4; mt++)
#pragma unroll
            for (int nt = 0; nt < 2; nt++) mma16816(acc[mt][nt], al[mt], bl[nt]);
    }

#pragma unroll
    for (int mt = 0; mt < 4; mt++) {
        int row = r0 + warpM * 64 + mt * 16 + (lane >> 2);
#pragma unroll
        for (int nt = 0; nt < 2; nt++) {
            int col = half * 256 + n0 + warpN * 16 + nt * 8 + 2 * (lane & 3);
            *(float2*)(g_s + (size_t)row * 512 + col) =
                make_float2(acc[mt][nt][0], acc[mt][nt][1]);
            *(float2*)(g_s + (size_t)(row + 8) * 512 + col) =
                make_float2(acc[mt][nt][2], acc[mt][nt][3]);
        }
    }
}

// ---------------- Kernel 3: topk + softmax (1 warp per row) ------------------
__global__ __launch_bounds__(512) void topk_kernel() {
    __shared__ __align__(16) float ss[16][512];
    int tid = threadIdx.x;
    int lane = tid & 31;
    int warp = tid >> 5;       // 0..15, one row each
    int r0 = blockIdx.x * 16;

#pragma unroll
    for (int i = 0; i < 4; i++) {
        int idx = tid + i * 512;
        int row = idx >> 7, c4 = idx & 127;
        ((float4*)ss[row])[c4] = ((const float4*)(g_s + (size_t)(r0 + row) * 512))[c4];
    }
    __syncthreads();

    int rr = warp;
    int r = r0 + rr;
    for (int list = 0; list < 2; list++) {
        float* src = ss[rr] + list * 256;
        float v[8];
#pragma unroll
        for (int j = 0; j < 8; j++) v[j] = src[lane + 32 * j];
#pragma unroll 1
        for (int t = 0; t < TK; t++) {
            float mv = v[0]; int mj = 0;
#pragma unroll
            for (int j = 1; j < 8; j++)
                if (v[j] > mv) { mv = v[j]; mj = j; }
            int mi = lane + (mj << 5);
#pragma unroll
            for (int off = 16; off; off >>= 1) {
                float ov = __shfl_xor_sync(0xFFFFFFFFu, mv, off);
                int   oi = __shfl_xor_sync(0xFFFFFFFFu, mi, off);
                if (ov > mv || (ov == mv && oi < mi)) { mv = ov; mi = oi; }
            }
            if (lane == 0) {
                ss[rr][list * 20 + t] = mv;
                ss[rr][list * 20 + 10 + t] = __int_as_float(mi);
            }
            if ((mi & 31) == lane) {
                int jj = mi >> 5;
#pragma unroll
                for (int j = 0; j < 8; j++)
                    if (j == jj) v[j] = NEG_INF;
            }
        }
    }
    __syncwarp();

    float cv[4]; int cp[4];
#pragma unroll
    for (int t = 0; t < 4; t++) {
        int p = lane + 32 * t;
        if (p < 100) {
            int i = p / 10, j = p - i * 10;
            cv[t] = ss[rr][i] + ss[rr][20 + j];
            cp[t] = p;
        } else { cv[t] = NEG_INF; cp[t] = 127; }
    }
    float m = 0.f, sum = 0.f, myval = 0.f;
    int myidx = 0;
#pragma unroll 1
    for (int t = 0; t < TK; t++) {
        float mv = cv[0]; int mp = cp[0];
#pragma unroll
        for (int u = 1; u < 4; u++)
            if (cv[u] > mv || (cv[u] == mv && cp[u] < mp)) { mv = cv[u]; mp = cp[u]; }
#pragma unroll
        for (int off = 16; off; off >>= 1) {
            float ov = __shfl_xor_sync(0xFFFFFFFFu, mv, off);
            int   op = __shfl_xor_sync(0xFFFFFFFFu, mp, off);
            if (ov > mv || (ov == mv && op < mp)) { mv = ov; mp = op; }
        }
        if (t == 0) m = mv;
        sum += expf(mv - m);
        int i = mp / 10, j = mp - i * 10;
        int ei = __float_as_int(ss[rr][10 + i]) * NSQ + __float_as_int(ss[rr][30 + j]);
        if (lane == t) { myval = mv; myidx = ei; }
#pragma unroll
        for (int u = 0; u < 4; u++)
            if (cp[u] == mp) cv[u] = NEG_INF;
    }
    if (lane < TK) {
        g_eidx[r * TK + lane] = myidx;
        g_ew[r * TK + lane]   = expf(myval - m) / sum;
    }
}

// ---------------- Kernel 4: expert gather + GELU + weighted combine ---------
__global__ __launch_bounds__(256) void expert_kernel(const float* __restrict__ x,
                                                     const float* __restrict__ W_up,
                                                     const float* __restrict__ W_down,
                                                     float* __restrict__ out) {
    __shared__ __align__(16) float xs[DIN];
    __shared__ float hs[80];
    __shared__ int   es[80];
    int token = blockIdx.x;
    int tid = threadIdx.x;

    ((float4*)xs)[tid] = ((const float4*)(x + (size_t)token * DIN))[tid];
    if (tid < 80) es[tid] = g_eidx[token * 80 + tid];
    __syncthreads();

    int warp = tid >> 5, lane = tid & 31;
    {
        const float4* wrow[TK];
#pragma unroll
        for (int k = 0; k < TK; k++)
            wrow[k] = (const float4*)(W_down + (size_t)es[warp * TK + k] * DIN);
        float acc[TK];
#pragma unroll
        for (int k = 0; k < TK; k++) acc[k] = 0.f;
        const float4* x4 = (const float4*)xs;
#pragma unroll
        for (int i = 0; i < 8; i++) {
            float4 v4 = x4[lane + i * 32];
#pragma unroll
            for (int k = 0; k < TK; k++) {
                float4 w4 = wrow[k][lane + i * 32];
                acc[k] += w4.x * v4.x + w4.y * v4.y + w4.z * v4.z + w4.w * v4.w;
            }
        }
#pragma unroll
        for (int k = 0; k < TK; k++) {
            float a = acc[k];
#pragma unroll
            for (int off = 16; off; off >>= 1) a += __shfl_xor_sync(0xFFFFFFFFu, a, off);
            if (lane == k) {
                float g = 0.5f * a * (1.0f + erff(a * 0.70710678118654752f));
                hs[warp * TK + k] = g * g_ew[token * 80 + warp * TK + k];
            }
        }
    }
    __syncthreads();

    float4 acc4 = make_float4(0.f, 0.f, 0.f, 0.f);
#pragma unroll 10
    for (int e = 0; e < 80; e++) {
        float h = hs[e];
        float4 u4 = ((const float4*)(W_up + (size_t)es[e] * DIN))[tid];
        acc4.x += h * u4.x; acc4.y += h * u4.y;
        acc4.z += h * u4.z; acc4.w += h * u4.w;
    }
    ((float4*)(out + (size_t)token * DIN))[tid] = acc4;
}

// ---------------- launch ----------------------------------------------------
extern "C" void kernel_launch(void* const* d_in, const int* in_sizes, int n_in,
                              void* d_out, int out_size) {
    const float* x      = (const float*)d_in[0];
    const float* Wq     = (const float*)d_in[1];
    const float* bq     = (const float*)d_in[2];
    const float* K1     = (const float*)d_in[3];
    const float* K2     = (const float*)d_in[4];
    const float* W_up   = (const float*)d_in[5];
    const float* W_down = (const float*)d_in[6];
    float* out = (float*)d_out;

    cudaFuncSetAttribute(gemm_tc_kernel, cudaFuncAttributeMaxDynamicSharedMemorySize, GEMM_SMEM);
    cudaFuncSetAttribute(score_kernel, cudaFuncAttributeMaxDynamicSharedMemorySize, SCORE_SMEM);

    split_x_kernel<<<(TOKENS * DIN) / 1024, 256>>>(x);
    split_wq_kernel<<<dim3(NQ / 32, DIN / 32), 256>>>(Wq);
    ksplit_kernel<<<128, 256>>>(K1, K2);
    gemm_tc_kernel<<<dim3(NQ / 128, TOKENS / 128), 256, GEMM_SMEM>>>(bq);
    score_kernel<<<dim3(2, 4, NR / 128), 256, SCORE_SMEM>>>();
    topk_kernel<<<NR / 16, 512>>>();
    expert_kernel<<<TOKENS, 256>>>(x, W_up, W_down, out);
}